// round 1
// baseline (speedup 1.0000x reference)
#include <cuda_runtime.h>
#include <cuda_bf16.h>
#include <math.h>

#define NN 50000
#define EE 500000
#define DD 128
#define HH 8
#define HDIM 16
#define LL 2
#define FFD 512
#define NE (EE + NN)

// ---------------- scratch (device globals; no allocations allowed) ----------
__device__ float  g_xn[NN * DD];          // LayerNorm output
__device__ float  g_qkv[NN * 3 * DD];     // fused Q|K|V per node
__device__ float  g_aggr[NN * DD];        // attention aggregation
__device__ float  g_h[NN * FFD];          // FFN hidden
__device__ float  g_ex[NE * HH];          // per-edge exp(logit)
__device__ float  g_s[NN * HH];           // per-node softmax denom
__device__ float  g_deg[NN];
__device__ float  g_degn[NN];
__device__ double g_stats[2];             // sum, sumsq of deg
__device__ float  g_weff[DD * 3 * DD];    // folded (I+Wpos)@[Wq|Wk|Wv]
__device__ float  g_beff[3 * DD];
__device__ float  g_wdegeff[3 * DD];

// ---------------- degree kernels --------------------------------------------
__global__ void k_deg_init(float* deg) {
    int i = blockIdx.x * blockDim.x + threadIdx.x;
    if (i < NN) deg[i] = 1.0f;   // self loop
}
__global__ void k_deg_count(const int* __restrict__ ei, float* deg) {
    int e = blockIdx.x * blockDim.x + threadIdx.x;
    if (e < EE) atomicAdd(&deg[ei[e]], 1.0f);
}
__global__ void k_stats_zero(double* st) { st[0] = 0.0; st[1] = 0.0; }
__global__ void k_deg_reduce(const float* __restrict__ deg, double* st) {
    __shared__ double ss[256], sq[256];
    int t = threadIdx.x;
    double s = 0.0, q = 0.0;
    for (int i = blockIdx.x * blockDim.x + t; i < NN; i += gridDim.x * blockDim.x) {
        double d = (double)deg[i];
        s += d; q += d * d;
    }
    ss[t] = s; sq[t] = q;
    __syncthreads();
    for (int o = 128; o > 0; o >>= 1) {
        if (t < o) { ss[t] += ss[t + o]; sq[t] += sq[t + o]; }
        __syncthreads();
    }
    if (t == 0) { atomicAdd(&st[0], ss[0]); atomicAdd(&st[1], sq[0]); }
}
__global__ void k_deg_norm(const float* __restrict__ deg, const double* __restrict__ st,
                           float* __restrict__ degn) {
    int i = blockIdx.x * blockDim.x + threadIdx.x;
    if (i >= NN) return;
    double mean = st[0] / (double)NN;
    double var  = (st[1] - st[0] * st[0] / (double)NN) / (double)(NN - 1);
    float  sd   = (float)sqrt(var);
    degn[i] = (deg[i] - (float)mean) / (sd + 1e-6f);
}

// ---------------- folded effective weights ----------------------------------
// Weff[k][j] = W[k][jj] + sum_m Wpos[k][m] * W[m][jj]     (j in [0,384), jj=j&127)
// beff[j]    = b[jj] + sum_m (bpos[m]+bdeg[m]) * W[m][jj]
// wdegeff[j] = sum_m Wdeg[m] * W[m][jj]
__global__ void k_weff(const float* __restrict__ Wq, const float* __restrict__ Wk,
                       const float* __restrict__ Wv, const float* __restrict__ Wpos,
                       const float* __restrict__ Wdeg,
                       const float* __restrict__ bq, const float* __restrict__ bk,
                       const float* __restrict__ bv, const float* __restrict__ bpos,
                       const float* __restrict__ bdeg,
                       float* __restrict__ weff, float* __restrict__ beff,
                       float* __restrict__ wdegeff) {
    int j = blockIdx.x;             // 0..383
    int t = threadIdx.x;            // 0..127
    const float* W  = (j < DD) ? Wq : ((j < 2 * DD) ? Wk : Wv);
    const float* bb = (j < DD) ? bq : ((j < 2 * DD) ? bk : bv);
    int jj = j & (DD - 1);
    __shared__ float col[DD];
    col[t] = W[t * DD + jj];
    __syncthreads();
    float acc = col[t];
    #pragma unroll 8
    for (int m = 0; m < DD; m++) acc += Wpos[t * DD + m] * col[m];
    weff[t * (3 * DD) + j] = acc;
    if (t == 0) {
        float s = 0.f;
        for (int m = 0; m < DD; m++) s += (bpos[m] + bdeg[m]) * col[m];
        beff[j] = s + bb[jj];
    }
    if (t == 1) {
        float s = 0.f;
        for (int m = 0; m < DD; m++) s += Wdeg[m] * col[m];
        wdegeff[j] = s;
    }
}

// ---------------- LayerNorm (warp per node) ----------------------------------
__global__ void k_layernorm(const float* __restrict__ x, const float* __restrict__ g,
                            const float* __restrict__ b, float* __restrict__ out) {
    int node = (blockIdx.x * blockDim.x + threadIdx.x) >> 5;
    int lane = threadIdx.x & 31;
    if (node >= NN) return;
    const float4 v = *(const float4*)(x + (long)node * DD + lane * 4);
    float s = v.x + v.y + v.z + v.w;
    #pragma unroll
    for (int o = 16; o > 0; o >>= 1) s += __shfl_xor_sync(0xffffffffu, s, o);
    float mu = s * (1.0f / DD);
    float dx = v.x - mu, dy = v.y - mu, dz = v.z - mu, dw = v.w - mu;
    float q = dx * dx + dy * dy + dz * dz + dw * dw;
    #pragma unroll
    for (int o = 16; o > 0; o >>= 1) q += __shfl_xor_sync(0xffffffffu, q, o);
    float rs = rsqrtf(q * (1.0f / DD) + 1e-5f);
    const float4 gg = *(const float4*)(g + lane * 4);
    const float4 bb = *(const float4*)(b + lane * 4);
    float4 o4;
    o4.x = dx * rs * gg.x + bb.x;
    o4.y = dy * rs * gg.y + bb.y;
    o4.z = dz * rs * gg.z + bb.z;
    o4.w = dw * rs * gg.w + bb.w;
    *(float4*)(out + (long)node * DD + lane * 4) = o4;
}

// ---------------- zero scratch ------------------------------------------------
__global__ void k_zero2(float* a, int na, float* b, int nb) {
    int i = blockIdx.x * blockDim.x + threadIdx.x;
    if (i < na) a[i] = 0.0f;
    if (i < nb) b[i] = 0.0f;
}

// ---------------- SGEMM with fused epilogues ----------------------------------
// C[M,Ncols] = A[M,K] @ B[K,Ncols] (+ epilogue). B row-major K x Ncols.
// mode 0: + bias[j] + degn[i]*wdeg[j]        (QKV)
// mode 1: + bias[j] + C[i,j]   (residual; C read-then-write by owning thread)
// mode 2: gelu( + bias[j] )                  (FFN hidden)
#define BM 64
#define BN 64
#define BKT 16
__global__ __launch_bounds__(256) void sgemm_ep(
    const float* __restrict__ A, const float* __restrict__ B, float* C,
    const float* __restrict__ bias, const float* __restrict__ wdegv,
    const float* __restrict__ degn, int M, int Ncols, int K, int mode) {
    __shared__ float As[BKT][BM + 4];
    __shared__ float Bs[BKT][BN + 4];
    int tid = threadIdx.x;
    int tx = tid & 15, ty = tid >> 4;
    int rowBase = blockIdx.y * BM;
    int colBase = blockIdx.x * BN;
    float acc[4][4] = {};
    for (int k0 = 0; k0 < K; k0 += BKT) {
        #pragma unroll
        for (int i = 0; i < 4; i++) {
            int idx = tid + i * 256;
            int r = idx >> 4, c = idx & 15;
            int gr = rowBase + r;
            As[c][r] = (gr < M) ? A[(long)gr * K + k0 + c] : 0.0f;
        }
        #pragma unroll
        for (int i = 0; i < 4; i++) {
            int idx = tid + i * 256;
            int r = idx >> 6, c = idx & 63;
            Bs[r][c] = B[(long)(k0 + r) * Ncols + colBase + c];
        }
        __syncthreads();
        #pragma unroll
        for (int k = 0; k < BKT; k++) {
            float4 a4 = *(const float4*)&As[k][ty * 4];
            float4 b4 = *(const float4*)&Bs[k][tx * 4];
            float a[4] = {a4.x, a4.y, a4.z, a4.w};
            float b[4] = {b4.x, b4.y, b4.z, b4.w};
            #pragma unroll
            for (int i = 0; i < 4; i++)
                #pragma unroll
                for (int j = 0; j < 4; j++) acc[i][j] += a[i] * b[j];
        }
        __syncthreads();
    }
    #pragma unroll
    for (int i = 0; i < 4; i++) {
        int gr = rowBase + ty * 4 + i;
        if (gr >= M) continue;
        float dn = (mode == 0) ? degn[gr] : 0.0f;
        #pragma unroll
        for (int j = 0; j < 4; j++) {
            int gc = colBase + tx * 4 + j;
            float v = acc[i][j] + bias[gc];
            if (mode == 0) {
                v += dn * wdegv[gc];
            } else if (mode == 1) {
                v += C[(long)gr * Ncols + gc];
            } else { // gelu exact
                v = 0.5f * v * (1.0f + erff(v * 0.70710678118654752f));
            }
            C[(long)gr * Ncols + gc] = v;
        }
    }
}

// ---------------- attention pass 1: logits + exp + denom ----------------------
__global__ void k_att_logits(const int* __restrict__ ei, const float* __restrict__ qkv,
                             float* __restrict__ exb, float* __restrict__ s) {
    int w = (blockIdx.x * blockDim.x + threadIdx.x) >> 5;
    int lane = threadIdx.x & 31;
    if (w >= NE) return;
    int src, dst;
    if (w < EE) { src = ei[w]; dst = ei[EE + w]; }
    else        { src = dst = w - EE; }
    const float4 q4 = *(const float4*)(qkv + (long)dst * 384 + lane * 4);
    const float4 k4 = *(const float4*)(qkv + (long)src * 384 + 128 + lane * 4);
    float p = q4.x * k4.x + q4.y * k4.y + q4.z * k4.z + q4.w * k4.w;
    p += __shfl_xor_sync(0xffffffffu, p, 1);
    p += __shfl_xor_sync(0xffffffffu, p, 2);
    if ((lane & 3) == 0) {
        float att = p * 0.25f;                      // / sqrt(16)
        att = fminf(fmaxf(att, -50.0f), 50.0f);
        float ex = __expf(att);                     // max e^50, no overflow
        int h = lane >> 2;
        exb[(long)w * HH + h] = ex;
        atomicAdd(&s[dst * HH + h], ex);
    }
}

// ---------------- attention pass 2: weighted aggregation ----------------------
__global__ void k_att_aggr(const int* __restrict__ ei, const float* __restrict__ qkv,
                           const float* __restrict__ exb, const float* __restrict__ s,
                           float* __restrict__ aggr) {
    int w = (blockIdx.x * blockDim.x + threadIdx.x) >> 5;
    int lane = threadIdx.x & 31;
    if (w >= NE) return;
    int src, dst;
    if (w < EE) { src = ei[w]; dst = ei[EE + w]; }
    else        { src = dst = w - EE; }
    int h = lane >> 2;
    float alpha = exb[(long)w * HH + h] / (s[dst * HH + h] + 1e-16f);
    const float4 v4 = *(const float4*)(qkv + (long)src * 384 + 256 + lane * 4);
    float* dptr = aggr + (long)dst * DD + lane * 4;
    asm volatile("red.global.add.v4.f32 [%0], {%1,%2,%3,%4};"
                 :: "l"(dptr), "f"(v4.x * alpha), "f"(v4.y * alpha),
                    "f"(v4.z * alpha), "f"(v4.w * alpha) : "memory");
}

// ---------------- driver -------------------------------------------------------
extern "C" void kernel_launch(void* const* d_in, const int* in_sizes, int n_in,
                              void* d_out, int out_size) {
    // metadata order = setup_inputs() dict order
    const float* x    = (const float*)d_in[0];
    const int*   ei   = (const int*)d_in[1];
    const float* Wq   = (const float*)d_in[2];
    const float* Wk   = (const float*)d_in[3];
    const float* Wv   = (const float*)d_in[4];
    const float* Wo   = (const float*)d_in[5];
    const float* Wpos = (const float*)d_in[6];
    const float* Wdeg = (const float*)d_in[7];
    const float* W1   = (const float*)d_in[8];
    const float* W2   = (const float*)d_in[9];
    const float* bq   = (const float*)d_in[10];
    const float* bk   = (const float*)d_in[11];
    const float* bv   = (const float*)d_in[12];
    const float* bo   = (const float*)d_in[13];
    const float* bpos = (const float*)d_in[14];
    const float* bdeg = (const float*)d_in[15];
    const float* ln1b = (const float*)d_in[16];
    const float* ln2b = (const float*)d_in[17];
    const float* b1   = (const float*)d_in[18];
    const float* b2   = (const float*)d_in[19];
    const float* ln1g = (const float*)d_in[20];
    const float* ln2g = (const float*)d_in[21];
    float* xbuf = (float*)d_out;

    float *xn, *qkv, *aggr, *hb, *exb, *sb, *deg, *degn, *weff, *beff, *wde;
    double* stats;
    cudaGetSymbolAddress((void**)&xn,    g_xn);
    cudaGetSymbolAddress((void**)&qkv,   g_qkv);
    cudaGetSymbolAddress((void**)&aggr,  g_aggr);
    cudaGetSymbolAddress((void**)&hb,    g_h);
    cudaGetSymbolAddress((void**)&exb,   g_ex);
    cudaGetSymbolAddress((void**)&sb,    g_s);
    cudaGetSymbolAddress((void**)&deg,   g_deg);
    cudaGetSymbolAddress((void**)&degn,  g_degn);
    cudaGetSymbolAddress((void**)&weff,  g_weff);
    cudaGetSymbolAddress((void**)&beff,  g_beff);
    cudaGetSymbolAddress((void**)&wde,   g_wdegeff);
    cudaGetSymbolAddress((void**)&stats, g_stats);

    cudaMemcpyAsync(xbuf, x, (size_t)NN * DD * sizeof(float), cudaMemcpyDeviceToDevice);

    // degree + standardization (layer-independent)
    k_deg_init<<<(NN + 255) / 256, 256>>>(deg);
    k_deg_count<<<(EE + 255) / 256, 256>>>(ei, deg);
    k_stats_zero<<<1, 1>>>(stats);
    k_deg_reduce<<<148, 256>>>(deg, stats);
    k_deg_norm<<<(NN + 255) / 256, 256>>>(deg, stats, degn);

    const int rowBlocks = (NN + BM - 1) / BM;
    const int lnBlocks  = (NN + 7) / 8;             // 8 warps/block, warp per node
    const int edgeBlocks = (NE + 7) / 8;            // warp per edge

    for (int l = 0; l < LL; l++) {
        const float* Wq_l = Wq + (size_t)l * DD * DD;
        const float* Wk_l = Wk + (size_t)l * DD * DD;
        const float* Wv_l = Wv + (size_t)l * DD * DD;
        const float* Wo_l = Wo + (size_t)l * DD * DD;
        const float* Wp_l = Wpos + (size_t)l * DD * DD;
        const float* Wd_l = Wdeg + (size_t)l * DD;
        const float* W1_l = W1 + (size_t)l * DD * FFD;
        const float* W2_l = W2 + (size_t)l * FFD * DD;

        k_weff<<<3 * DD, DD>>>(Wq_l, Wk_l, Wv_l, Wp_l, Wd_l,
                               bq + l * DD, bk + l * DD, bv + l * DD,
                               bpos + l * DD, bdeg + l * DD, weff, beff, wde);
        k_layernorm<<<lnBlocks, 256>>>(xbuf, ln1g + l * DD, ln1b + l * DD, xn);
        k_zero2<<<(NN * DD + 255) / 256, 256>>>(aggr, NN * DD, sb, NN * HH);

        // fused QKV GEMM with folded positional encoding
        sgemm_ep<<<dim3(3 * DD / BN, rowBlocks), 256>>>(
            xn, weff, qkv, beff, wde, degn, NN, 3 * DD, DD, 0);

        k_att_logits<<<edgeBlocks, 256>>>(ei, qkv, exb, sb);
        k_att_aggr<<<edgeBlocks, 256>>>(ei, qkv, exb, sb, aggr);

        // x += aggr @ Wo + bo
        sgemm_ep<<<dim3(DD / BN, rowBlocks), 256>>>(
            aggr, Wo_l, xbuf, bo + l * DD, nullptr, nullptr, NN, DD, DD, 1);

        // FFN
        k_layernorm<<<lnBlocks, 256>>>(xbuf, ln2g + l * DD, ln2b + l * DD, xn);
        sgemm_ep<<<dim3(FFD / BN, rowBlocks), 256>>>(
            xn, W1_l, hb, b1 + l * FFD, nullptr, nullptr, NN, FFD, DD, 2);
        sgemm_ep<<<dim3(DD / BN, rowBlocks), 256>>>(
            hb, W2_l, xbuf, b2 + l * DD, nullptr, nullptr, NN, DD, FFD, 1);
    }
}

// round 2
// speedup vs baseline: 1.6414x; 1.6414x over previous
#include <cuda_runtime.h>
#include <cuda_bf16.h>
#include <math.h>

#define NN 50000
#define EE 500000
#define DD 128
#define HH 8
#define LL 2
#define FFD 512
#define NE (EE + NN)

// ---------------- scratch (device globals; no allocations allowed) ----------
__device__ float  g_xn[NN * DD];
__device__ float  g_qkv[NN * 3 * DD];
__device__ float  g_aggr[NN * DD];
__device__ float  g_h[NN * FFD];
__device__ float  g_ex[NE * HH];
__device__ float  g_s[NN * HH];
__device__ float  g_deg[NN];
__device__ float  g_degn[NN];
__device__ double g_stats[2];
__device__ float  g_weff[DD * 3 * DD];
__device__ float  g_beff[3 * DD];
__device__ float  g_wdegeff[3 * DD];

// ---------------- degree kernels --------------------------------------------
__global__ void k_deg_init(float* deg) {
    int i = blockIdx.x * blockDim.x + threadIdx.x;
    if (i < NN) deg[i] = 1.0f;
}
__global__ void k_deg_count(const int* __restrict__ ei, float* deg) {
    int e = blockIdx.x * blockDim.x + threadIdx.x;
    if (e < EE) atomicAdd(&deg[ei[e]], 1.0f);
}
__global__ void k_stats_zero(double* st) { st[0] = 0.0; st[1] = 0.0; }
__global__ void k_deg_reduce(const float* __restrict__ deg, double* st) {
    __shared__ double ss[256], sq[256];
    int t = threadIdx.x;
    double s = 0.0, q = 0.0;
    for (int i = blockIdx.x * blockDim.x + t; i < NN; i += gridDim.x * blockDim.x) {
        double d = (double)deg[i];
        s += d; q += d * d;
    }
    ss[t] = s; sq[t] = q;
    __syncthreads();
    for (int o = 128; o > 0; o >>= 1) {
        if (t < o) { ss[t] += ss[t + o]; sq[t] += sq[t + o]; }
        __syncthreads();
    }
    if (t == 0) { atomicAdd(&st[0], ss[0]); atomicAdd(&st[1], sq[0]); }
}
__global__ void k_deg_norm(const float* __restrict__ deg, const double* __restrict__ st,
                           float* __restrict__ degn) {
    int i = blockIdx.x * blockDim.x + threadIdx.x;
    if (i >= NN) return;
    double mean = st[0] / (double)NN;
    double var  = (st[1] - st[0] * st[0] / (double)NN) / (double)(NN - 1);
    float  sd   = (float)sqrt(var);
    degn[i] = (deg[i] - (float)mean) / (sd + 1e-6f);
}

// ---------------- folded effective weights ----------------------------------
__global__ void k_weff(const float* __restrict__ Wq, const float* __restrict__ Wk,
                       const float* __restrict__ Wv, const float* __restrict__ Wpos,
                       const float* __restrict__ Wdeg,
                       const float* __restrict__ bq, const float* __restrict__ bk,
                       const float* __restrict__ bv, const float* __restrict__ bpos,
                       const float* __restrict__ bdeg,
                       float* __restrict__ weff, float* __restrict__ beff,
                       float* __restrict__ wdegeff) {
    int j = blockIdx.x;
    int t = threadIdx.x;
    const float* W  = (j < DD) ? Wq : ((j < 2 * DD) ? Wk : Wv);
    const float* bb = (j < DD) ? bq : ((j < 2 * DD) ? bk : bv);
    int jj = j & (DD - 1);
    __shared__ float col[DD];
    col[t] = W[t * DD + jj];
    __syncthreads();
    float acc = col[t];
    #pragma unroll 8
    for (int m = 0; m < DD; m++) acc += Wpos[t * DD + m] * col[m];
    weff[t * (3 * DD) + j] = acc;
    if (t == 0) {
        float s = 0.f;
        for (int m = 0; m < DD; m++) s += (bpos[m] + bdeg[m]) * col[m];
        beff[j] = s + bb[jj];
    }
    if (t == 1) {
        float s = 0.f;
        for (int m = 0; m < DD; m++) s += Wdeg[m] * col[m];
        wdegeff[j] = s;
    }
}

// ---------------- LayerNorm (warp per node) ----------------------------------
__global__ void k_layernorm(const float* __restrict__ x, const float* __restrict__ g,
                            const float* __restrict__ b, float* __restrict__ out) {
    int node = (blockIdx.x * blockDim.x + threadIdx.x) >> 5;
    int lane = threadIdx.x & 31;
    if (node >= NN) return;
    const float4 v = *(const float4*)(x + (long)node * DD + lane * 4);
    float s = v.x + v.y + v.z + v.w;
    #pragma unroll
    for (int o = 16; o > 0; o >>= 1) s += __shfl_xor_sync(0xffffffffu, s, o);
    float mu = s * (1.0f / DD);
    float dx = v.x - mu, dy = v.y - mu, dz = v.z - mu, dw = v.w - mu;
    float q = dx * dx + dy * dy + dz * dz + dw * dw;
    #pragma unroll
    for (int o = 16; o > 0; o >>= 1) q += __shfl_xor_sync(0xffffffffu, q, o);
    float rs = rsqrtf(q * (1.0f / DD) + 1e-5f);
    const float4 gg = *(const float4*)(g + lane * 4);
    const float4 bb = *(const float4*)(b + lane * 4);
    float4 o4;
    o4.x = dx * rs * gg.x + bb.x;
    o4.y = dy * rs * gg.y + bb.y;
    o4.z = dz * rs * gg.z + bb.z;
    o4.w = dw * rs * gg.w + bb.w;
    *(float4*)(out + (long)node * DD + lane * 4) = o4;
}

__global__ void k_zero2(float* a, int na, float* b, int nb) {
    int i = blockIdx.x * blockDim.x + threadIdx.x;
    if (i < na) a[i] = 0.0f;
    if (i < nb) b[i] = 0.0f;
}

// ---------------- TF32 tensor-core GEMM with fused epilogues ------------------
// C[M,N] = A[M,K] @ B[K,N] (+ epilogue). A,B,C row-major fp32.
// mode 0: + bias[j] + degn[i]*wdeg[j]   (QKV + folded pos-enc)
// mode 1: + bias[j] + C[i,j]            (residual add)
// mode 2: gelu(+ bias[j])               (FFN hidden)
#define BM 128
#define BN 64
#define BK 32
#define APAD 4
#define BPAD 4

__device__ __forceinline__ unsigned f2tf32(float f) {
    unsigned r;
    asm("cvt.rna.tf32.f32 %0, %1;" : "=r"(r) : "f"(f));
    return r;
}

__global__ __launch_bounds__(256) void gemm_tf32(
    const float* __restrict__ A, const float* __restrict__ B, float* C,
    const float* __restrict__ bias, const float* __restrict__ wdegv,
    const float* __restrict__ degn, int M, int N, int K, int mode) {
    __shared__ float As[BM][BK + APAD];   // tf32 bit patterns
    __shared__ float Bs[BK][BN + BPAD];

    const int tid  = threadIdx.x;
    const int warp = tid >> 5;
    const int lane = tid & 31;
    const int wm = warp >> 1;        // 0..3  (M direction, 32 rows each)
    const int wn = warp & 1;         // 0..1  (N direction, 32 cols each)
    const int g  = lane >> 2;        // group id 0..7
    const int q  = lane & 3;         // thread-in-group 0..3

    const int rowBase = blockIdx.y * BM;
    const int colBase = blockIdx.x * BN;

    float acc[2][4][4];
    #pragma unroll
    for (int i = 0; i < 2; i++)
        #pragma unroll
        for (int j = 0; j < 4; j++)
            #pragma unroll
            for (int k = 0; k < 4; k++) acc[i][j][k] = 0.0f;

    const int ar = tid >> 3;          // 0..31
    const int ac = (tid & 7) * 4;     // 0..28

    for (int k0 = 0; k0 < K; k0 += BK) {
        // load A tile 128x32 (16 floats / thread)
        #pragma unroll
        for (int i = 0; i < 4; i++) {
            int row  = ar + i * 32;
            int grow = rowBase + row;
            float4 v = make_float4(0.f, 0.f, 0.f, 0.f);
            if (grow < M) v = *(const float4*)(A + (long)grow * K + k0 + ac);
            float4 t;
            t.x = __uint_as_float(f2tf32(v.x));
            t.y = __uint_as_float(f2tf32(v.y));
            t.z = __uint_as_float(f2tf32(v.z));
            t.w = __uint_as_float(f2tf32(v.w));
            *(float4*)&As[row][ac] = t;
        }
        // load B tile 32x64 (8 floats / thread)
        #pragma unroll
        for (int i = 0; i < 2; i++) {
            int fid = tid + i * 256;
            int row = fid >> 4;
            int col = (fid & 15) * 4;
            float4 v = *(const float4*)(B + (long)(k0 + row) * N + colBase + col);
            float4 t;
            t.x = __uint_as_float(f2tf32(v.x));
            t.y = __uint_as_float(f2tf32(v.y));
            t.z = __uint_as_float(f2tf32(v.z));
            t.w = __uint_as_float(f2tf32(v.w));
            *(float4*)&Bs[row][col] = t;
        }
        __syncthreads();

        #pragma unroll
        for (int kk = 0; kk < BK; kk += 8) {
            unsigned a_frag[2][4];
            #pragma unroll
            for (int mt = 0; mt < 2; mt++) {
                int row = wm * 32 + mt * 16 + g;
                a_frag[mt][0] = __float_as_uint(As[row][kk + q]);
                a_frag[mt][1] = __float_as_uint(As[row + 8][kk + q]);
                a_frag[mt][2] = __float_as_uint(As[row][kk + q + 4]);
                a_frag[mt][3] = __float_as_uint(As[row + 8][kk + q + 4]);
            }
            unsigned b_frag[4][2];
            #pragma unroll
            for (int nt = 0; nt < 4; nt++) {
                int col = wn * 32 + nt * 8 + g;
                b_frag[nt][0] = __float_as_uint(Bs[kk + q][col]);
                b_frag[nt][1] = __float_as_uint(Bs[kk + q + 4][col]);
            }
            #pragma unroll
            for (int mt = 0; mt < 2; mt++)
                #pragma unroll
                for (int nt = 0; nt < 4; nt++) {
                    asm volatile(
                        "mma.sync.aligned.m16n8k8.row.col.f32.tf32.tf32.f32 "
                        "{%0,%1,%2,%3}, {%4,%5,%6,%7}, {%8,%9}, {%0,%1,%2,%3};"
                        : "+f"(acc[mt][nt][0]), "+f"(acc[mt][nt][1]),
                          "+f"(acc[mt][nt][2]), "+f"(acc[mt][nt][3])
                        : "r"(a_frag[mt][0]), "r"(a_frag[mt][1]),
                          "r"(a_frag[mt][2]), "r"(a_frag[mt][3]),
                          "r"(b_frag[nt][0]), "r"(b_frag[nt][1]));
                }
        }
        __syncthreads();
    }

    // epilogue: c0,c1 -> (row g, cols 2q,2q+1); c2,c3 -> (row g+8, same)
    #pragma unroll
    for (int mt = 0; mt < 2; mt++) {
        #pragma unroll
        for (int half = 0; half < 2; half++) {
            int gr = rowBase + wm * 32 + mt * 16 + g + half * 8;
            if (gr >= M) continue;
            float dn = (mode == 0) ? degn[gr] : 0.0f;
            #pragma unroll
            for (int nt = 0; nt < 4; nt++) {
                int gc = colBase + wn * 32 + nt * 8 + q * 2;
                float v0 = acc[mt][nt][half * 2 + 0] + bias[gc];
                float v1 = acc[mt][nt][half * 2 + 1] + bias[gc + 1];
                float* cp = C + (long)gr * N + gc;
                if (mode == 0) {
                    v0 += dn * wdegv[gc];
                    v1 += dn * wdegv[gc + 1];
                } else if (mode == 1) {
                    float2 old = *(const float2*)cp;
                    v0 += old.x;
                    v1 += old.y;
                } else {
                    v0 = 0.5f * v0 * (1.0f + erff(v0 * 0.70710678118654752f));
                    v1 = 0.5f * v1 * (1.0f + erff(v1 * 0.70710678118654752f));
                }
                *(float2*)cp = make_float2(v0, v1);
            }
        }
    }
}

// ---------------- attention pass 1: logits + exp + denom ----------------------
__global__ void k_att_logits(const int* __restrict__ ei, const float* __restrict__ qkv,
                             float* __restrict__ exb, float* __restrict__ s) {
    int w = (blockIdx.x * blockDim.x + threadIdx.x) >> 5;
    int lane = threadIdx.x & 31;
    if (w >= NE) return;
    int src, dst;
    if (w < EE) { src = ei[w]; dst = ei[EE + w]; }
    else        { src = dst = w - EE; }
    const float4 q4 = *(const float4*)(qkv + (long)dst * 384 + lane * 4);
    const float4 k4 = *(const float4*)(qkv + (long)src * 384 + 128 + lane * 4);
    float p = q4.x * k4.x + q4.y * k4.y + q4.z * k4.z + q4.w * k4.w;
    p += __shfl_xor_sync(0xffffffffu, p, 1);
    p += __shfl_xor_sync(0xffffffffu, p, 2);
    if ((lane & 3) == 0) {
        float att = p * 0.25f;
        att = fminf(fmaxf(att, -50.0f), 50.0f);
        float ex = __expf(att);
        int h = lane >> 2;
        exb[(long)w * HH + h] = ex;
        atomicAdd(&s[dst * HH + h], ex);
    }
}

// ---------------- attention pass 2: weighted aggregation ----------------------
__global__ void k_att_aggr(const int* __restrict__ ei, const float* __restrict__ qkv,
                           const float* __restrict__ exb, const float* __restrict__ s,
                           float* __restrict__ aggr) {
    int w = (blockIdx.x * blockDim.x + threadIdx.x) >> 5;
    int lane = threadIdx.x & 31;
    if (w >= NE) return;
    int src, dst;
    if (w < EE) { src = ei[w]; dst = ei[EE + w]; }
    else        { src = dst = w - EE; }
    int h = lane >> 2;
    float alpha = exb[(long)w * HH + h] / (s[dst * HH + h] + 1e-16f);
    const float4 v4 = *(const float4*)(qkv + (long)src * 384 + 256 + lane * 4);
    float* dptr = aggr + (long)dst * DD + lane * 4;
    asm volatile("red.global.add.v4.f32 [%0], {%1,%2,%3,%4};"
                 :: "l"(dptr), "f"(v4.x * alpha), "f"(v4.y * alpha),
                    "f"(v4.z * alpha), "f"(v4.w * alpha) : "memory");
}

// ---------------- driver -------------------------------------------------------
extern "C" void kernel_launch(void* const* d_in, const int* in_sizes, int n_in,
                              void* d_out, int out_size) {
    const float* x    = (const float*)d_in[0];
    const int*   ei   = (const int*)d_in[1];
    const float* Wq   = (const float*)d_in[2];
    const float* Wk   = (const float*)d_in[3];
    const float* Wv   = (const float*)d_in[4];
    const float* Wo   = (const float*)d_in[5];
    const float* Wpos = (const float*)d_in[6];
    const float* Wdeg = (const float*)d_in[7];
    const float* W1   = (const float*)d_in[8];
    const float* W2   = (const float*)d_in[9];
    const float* bq   = (const float*)d_in[10];
    const float* bk   = (const float*)d_in[11];
    const float* bv   = (const float*)d_in[12];
    const float* bo   = (const float*)d_in[13];
    const float* bpos = (const float*)d_in[14];
    const float* bdeg = (const float*)d_in[15];
    const float* ln1b = (const float*)d_in[16];
    const float* ln2b = (const float*)d_in[17];
    const float* b1   = (const float*)d_in[18];
    const float* b2   = (const float*)d_in[19];
    const float* ln1g = (const float*)d_in[20];
    const float* ln2g = (const float*)d_in[21];
    float* xbuf = (float*)d_out;

    float *xn, *qkv, *aggr, *hb, *exb, *sb, *deg, *degn, *weff, *beff, *wde;
    double* stats;
    cudaGetSymbolAddress((void**)&xn,    g_xn);
    cudaGetSymbolAddress((void**)&qkv,   g_qkv);
    cudaGetSymbolAddress((void**)&aggr,  g_aggr);
    cudaGetSymbolAddress((void**)&hb,    g_h);
    cudaGetSymbolAddress((void**)&exb,   g_ex);
    cudaGetSymbolAddress((void**)&sb,    g_s);
    cudaGetSymbolAddress((void**)&deg,   g_deg);
    cudaGetSymbolAddress((void**)&degn,  g_degn);
    cudaGetSymbolAddress((void**)&weff,  g_weff);
    cudaGetSymbolAddress((void**)&beff,  g_beff);
    cudaGetSymbolAddress((void**)&wde,   g_wdegeff);
    cudaGetSymbolAddress((void**)&stats, g_stats);

    cudaMemcpyAsync(xbuf, x, (size_t)NN * DD * sizeof(float), cudaMemcpyDeviceToDevice);

    k_deg_init<<<(NN + 255) / 256, 256>>>(deg);
    k_deg_count<<<(EE + 255) / 256, 256>>>(ei, deg);
    k_stats_zero<<<1, 1>>>(stats);
    k_deg_reduce<<<148, 256>>>(deg, stats);
    k_deg_norm<<<(NN + 255) / 256, 256>>>(deg, stats, degn);

    const int rowBlocks  = (NN + BM - 1) / BM;
    const int lnBlocks   = (NN + 7) / 8;
    const int edgeBlocks = (NE + 7) / 8;

    for (int l = 0; l < LL; l++) {
        const float* Wo_l = Wo + (size_t)l * DD * DD;
        const float* W1_l = W1 + (size_t)l * DD * FFD;
        const float* W2_l = W2 + (size_t)l * FFD * DD;

        k_weff<<<3 * DD, DD>>>(Wq + (size_t)l * DD * DD, Wk + (size_t)l * DD * DD,
                               Wv + (size_t)l * DD * DD, Wpos + (size_t)l * DD * DD,
                               Wdeg + (size_t)l * DD,
                               bq + l * DD, bk + l * DD, bv + l * DD,
                               bpos + l * DD, bdeg + l * DD, weff, beff, wde);
        k_layernorm<<<lnBlocks, 256>>>(xbuf, ln1g + l * DD, ln1b + l * DD, xn);
        k_zero2<<<(NN * DD + 255) / 256, 256>>>(aggr, NN * DD, sb, NN * HH);

        gemm_tf32<<<dim3(3 * DD / BN, rowBlocks), 256>>>(
            xn, weff, qkv, beff, wde, degn, NN, 3 * DD, DD, 0);

        k_att_logits<<<edgeBlocks, 256>>>(ei, qkv, exb, sb);
        k_att_aggr<<<edgeBlocks, 256>>>(ei, qkv, exb, sb, aggr);

        gemm_tf32<<<dim3(DD / BN, rowBlocks), 256>>>(
            aggr, Wo_l, xbuf, bo + l * DD, nullptr, nullptr, NN, DD, DD, 1);

        k_layernorm<<<lnBlocks, 256>>>(xbuf, ln2g + l * DD, ln2b + l * DD, xn);
        gemm_tf32<<<dim3(FFD / BN, rowBlocks), 256>>>(
            xn, W1_l, hb, b1 + l * FFD, nullptr, nullptr, NN, FFD, DD, 2);
        gemm_tf32<<<dim3(DD / BN, rowBlocks), 256>>>(
            hb, W2_l, xbuf, b2 + l * DD, nullptr, nullptr, NN, DD, FFD, 1);
    }
}

// round 3
// speedup vs baseline: 1.7664x; 1.0762x over previous
#include <cuda_runtime.h>
#include <cuda_bf16.h>
#include <math.h>

#define NN 50000
#define EE 500000
#define DD 128
#define HH 8
#define LL 2
#define FFD 512
#define NE (EE + NN)

// ---------------- scratch ----------------------------------------------------
__device__ float  g_xn[NN * DD];
__device__ float  g_qkv[NN * 3 * DD];
__device__ float  g_aggr[NN * DD];
__device__ float  g_h[NN * FFD];
__device__ float  g_ex[NE * HH];
__device__ float  g_s[NN * HH];
__device__ float  g_deg[NN];
__device__ float  g_degn[NN];
__device__ double g_stats[2];
__device__ float  g_weff[DD * 3 * DD];
__device__ float  g_beff[3 * DD];
__device__ float  g_wdegeff[3 * DD];
__device__ float  g_wo[DD * DD];
__device__ float  g_w1[DD * FFD];
__device__ float  g_w2[FFD * DD];

__device__ __forceinline__ unsigned f2tf32(float f) {
    unsigned r;
    asm("cvt.rna.tf32.f32 %0, %1;" : "=r"(r) : "f"(f));
    return r;
}
__device__ __forceinline__ float rnd32(float f) { return __uint_as_float(f2tf32(f)); }

// ---------------- prep: zero aggr/s, deg=1, stats=0 ---------------------------
__global__ void k_prep(float* aggr, float* s, float* deg, double* st) {
    int i = blockIdx.x * blockDim.x + threadIdx.x;
    if (i < NN * DD) aggr[i] = 0.f;
    if (i < NN * HH) s[i] = 0.f;
    if (i < NN) deg[i] = 1.f;
    if (i == 0) { st[0] = 0.0; st[1] = 0.0; }
}
__global__ void k_zero2(float* a, int na, float* b, int nb) {
    int i = blockIdx.x * blockDim.x + threadIdx.x;
    if (i < na) a[i] = 0.0f;
    if (i < nb) b[i] = 0.0f;
}

// ---------------- degree kernels ----------------------------------------------
__global__ void k_deg_count(const int* __restrict__ ei, float* deg) {
    int e = blockIdx.x * blockDim.x + threadIdx.x;
    if (e < EE) atomicAdd(&deg[ei[e]], 1.0f);
}
__global__ void k_deg_reduce(const float* __restrict__ deg, double* st) {
    __shared__ double ss[256], sq[256];
    int t = threadIdx.x;
    double s = 0.0, q = 0.0;
    for (int i = blockIdx.x * blockDim.x + t; i < NN; i += gridDim.x * blockDim.x) {
        double d = (double)deg[i];
        s += d; q += d * d;
    }
    ss[t] = s; sq[t] = q;
    __syncthreads();
    for (int o = 128; o > 0; o >>= 1) {
        if (t < o) { ss[t] += ss[t + o]; sq[t] += sq[t + o]; }
        __syncthreads();
    }
    if (t == 0) { atomicAdd(&st[0], ss[0]); atomicAdd(&st[1], sq[0]); }
}
__global__ void k_deg_norm(const float* __restrict__ deg, const double* __restrict__ st,
                           float* __restrict__ degn) {
    int i = blockIdx.x * blockDim.x + threadIdx.x;
    if (i >= NN) return;
    double mean = st[0] / (double)NN;
    double var  = (st[1] - st[0] * st[0] / (double)NN) / (double)(NN - 1);
    float  sd   = (float)sqrt(var);
    degn[i] = (deg[i] - (float)mean) / (sd + 1e-6f);
}

// ---------------- folded effective weights (tf32-rounded output) --------------
__global__ void k_weff(const float* __restrict__ Wq, const float* __restrict__ Wk,
                       const float* __restrict__ Wv, const float* __restrict__ Wpos,
                       const float* __restrict__ Wdeg,
                       const float* __restrict__ bq, const float* __restrict__ bk,
                       const float* __restrict__ bv, const float* __restrict__ bpos,
                       const float* __restrict__ bdeg,
                       float* __restrict__ weff, float* __restrict__ beff,
                       float* __restrict__ wdegeff) {
    int j = blockIdx.x;
    int t = threadIdx.x;
    const float* W  = (j < DD) ? Wq : ((j < 2 * DD) ? Wk : Wv);
    const float* bb = (j < DD) ? bq : ((j < 2 * DD) ? bk : bv);
    int jj = j & (DD - 1);
    __shared__ float col[DD];
    col[t] = W[t * DD + jj];
    __syncthreads();
    float acc = col[t];
    #pragma unroll 8
    for (int m = 0; m < DD; m++) acc += Wpos[t * DD + m] * col[m];
    weff[t * (3 * DD) + j] = rnd32(acc);
    if (t == 0) {
        float s = 0.f;
        for (int m = 0; m < DD; m++) s += (bpos[m] + bdeg[m]) * col[m];
        beff[j] = s + bb[jj];
    }
    if (t == 1) {
        float s = 0.f;
        for (int m = 0; m < DD; m++) s += Wdeg[m] * col[m];
        wdegeff[j] = s;
    }
}

// ---------------- round weights / buffers to tf32 ------------------------------
__global__ void k_roundw(const float* __restrict__ Wo, const float* __restrict__ W1,
                         const float* __restrict__ W2, float* wo, float* w1, float* w2) {
    int i = blockIdx.x * blockDim.x + threadIdx.x;
    if (i < DD * DD) wo[i] = rnd32(Wo[i]);
    if (i < DD * FFD) { w1[i] = rnd32(W1[i]); w2[i] = rnd32(W2[i]); }
}
__global__ void k_round_inplace(float* a, int n) {
    int i = blockIdx.x * blockDim.x + threadIdx.x;
    if (i < n) a[i] = rnd32(a[i]);
}

// ---------------- LayerNorm (warp per node, tf32-rounded output) ---------------
__global__ void k_layernorm(const float* __restrict__ x, const float* __restrict__ g,
                            const float* __restrict__ b, float* __restrict__ out) {
    int node = (blockIdx.x * blockDim.x + threadIdx.x) >> 5;
    int lane = threadIdx.x & 31;
    if (node >= NN) return;
    const float4 v = *(const float4*)(x + (long)node * DD + lane * 4);
    float s = v.x + v.y + v.z + v.w;
    #pragma unroll
    for (int o = 16; o > 0; o >>= 1) s += __shfl_xor_sync(0xffffffffu, s, o);
    float mu = s * (1.0f / DD);
    float dx = v.x - mu, dy = v.y - mu, dz = v.z - mu, dw = v.w - mu;
    float q = dx * dx + dy * dy + dz * dz + dw * dw;
    #pragma unroll
    for (int o = 16; o > 0; o >>= 1) q += __shfl_xor_sync(0xffffffffu, q, o);
    float rs = rsqrtf(q * (1.0f / DD) + 1e-5f);
    const float4 gg = *(const float4*)(g + lane * 4);
    const float4 bb = *(const float4*)(b + lane * 4);
    float4 o4;
    o4.x = rnd32(dx * rs * gg.x + bb.x);
    o4.y = rnd32(dy * rs * gg.y + bb.y);
    o4.z = rnd32(dz * rs * gg.z + bb.z);
    o4.w = rnd32(dw * rs * gg.w + bb.w);
    *(float4*)(out + (long)node * DD + lane * 4) = o4;
}

// ---------------- pipelined tf32 tensor-core GEMM ------------------------------
// C[M,N] = A[M,K] @ B[K,N] (+epilogue). Operands MUST be pre-rounded to tf32.
// mode 0: + bias[j]            mode 1: + bias[j] + C[i,j]
// mode 2: round(gelu(+ bias[j]))
#define BM 128
#define BN 128
#define BK 16
#define APAD 4
#define BPAD 8

__device__ __forceinline__ unsigned smemu32(const void* p) {
    return (unsigned)__cvta_generic_to_shared(p);
}

__global__ __launch_bounds__(256, 2) void gemm_tc(
    const float* __restrict__ A, const float* __restrict__ B, float* C,
    const float* __restrict__ bias, int M, int N, int K, int mode) {
    __shared__ float As[2][BM][BK + APAD];
    __shared__ float Bs[2][BK][BN + BPAD];

    const int tid  = threadIdx.x;
    const int warp = tid >> 5;
    const int lane = tid & 31;
    const int wm = warp >> 1;      // 0..3, 32 rows each
    const int wn = warp & 1;       // 0..1, 64 cols each
    const int g  = lane >> 2;
    const int q  = lane & 3;
    const int rowBase = blockIdx.y * BM;
    const int colBase = blockIdx.x * BN;

    float acc[2][8][4];
    #pragma unroll
    for (int i = 0; i < 2; i++)
        #pragma unroll
        for (int j = 0; j < 8; j++)
            #pragma unroll
            for (int k = 0; k < 4; k++) acc[i][j][k] = 0.0f;

    const int nk = K / BK;

    // stage loaders
    auto loadA = [&](int s, int k0) {
        #pragma unroll
        for (int i = 0; i < 2; i++) {
            int idx = tid + i * 256;
            int r = idx >> 2, c = (idx & 3) * 4;
            int grow = rowBase + r;
            const float* src = A + (long)(grow < M ? grow : M - 1) * K + k0 + c;
            int sz = (grow < M) ? 16 : 0;
            asm volatile("cp.async.cg.shared.global [%0], [%1], 16, %2;"
                         :: "r"(smemu32(&As[s][r][c])), "l"(src), "r"(sz));
        }
    };
    auto loadB = [&](int s, int k0) {
        #pragma unroll
        for (int i = 0; i < 2; i++) {
            int idx = tid + i * 256;
            int r = idx >> 5, c = (idx & 31) * 4;
            const float* src = B + (long)(k0 + r) * N + colBase + c;
            asm volatile("cp.async.cg.shared.global [%0], [%1], 16;"
                         :: "r"(smemu32(&Bs[s][r][c])), "l"(src));
        }
    };

    loadA(0, 0); loadB(0, 0);
    asm volatile("cp.async.commit_group;");

    for (int kb = 0; kb < nk; kb++) {
        int buf = kb & 1;
        if (kb + 1 < nk) {
            loadA(buf ^ 1, (kb + 1) * BK);
            loadB(buf ^ 1, (kb + 1) * BK);
            asm volatile("cp.async.commit_group;");
            asm volatile("cp.async.wait_group 1;");
        } else {
            asm volatile("cp.async.wait_group 0;");
        }
        __syncthreads();

        #pragma unroll
        for (int kk = 0; kk < BK; kk += 8) {
            unsigned a_frag[2][4];
            #pragma unroll
            for (int mt = 0; mt < 2; mt++) {
                int row = wm * 32 + mt * 16 + g;
                a_frag[mt][0] = __float_as_uint(As[buf][row][kk + q]);
                a_frag[mt][1] = __float_as_uint(As[buf][row + 8][kk + q]);
                a_frag[mt][2] = __float_as_uint(As[buf][row][kk + q + 4]);
                a_frag[mt][3] = __float_as_uint(As[buf][row + 8][kk + q + 4]);
            }
            unsigned b_frag[8][2];
            #pragma unroll
            for (int nt = 0; nt < 8; nt++) {
                int col = wn * 64 + nt * 8 + g;
                b_frag[nt][0] = __float_as_uint(Bs[buf][kk + q][col]);
                b_frag[nt][1] = __float_as_uint(Bs[buf][kk + q + 4][col]);
            }
            #pragma unroll
            for (int mt = 0; mt < 2; mt++)
                #pragma unroll
                for (int nt = 0; nt < 8; nt++) {
                    asm volatile(
                        "mma.sync.aligned.m16n8k8.row.col.f32.tf32.tf32.f32 "
                        "{%0,%1,%2,%3}, {%4,%5,%6,%7}, {%8,%9}, {%0,%1,%2,%3};"
                        : "+f"(acc[mt][nt][0]), "+f"(acc[mt][nt][1]),
                          "+f"(acc[mt][nt][2]), "+f"(acc[mt][nt][3])
                        : "r"(a_frag[mt][0]), "r"(a_frag[mt][1]),
                          "r"(a_frag[mt][2]), "r"(a_frag[mt][3]),
                          "r"(b_frag[nt][0]), "r"(b_frag[nt][1]));
                }
        }
        __syncthreads();
    }

    #pragma unroll
    for (int mt = 0; mt < 2; mt++) {
        #pragma unroll
        for (int half = 0; half < 2; half++) {
            int gr = rowBase + wm * 32 + mt * 16 + g + half * 8;
            if (gr >= M) continue;
            #pragma unroll
            for (int nt = 0; nt < 8; nt++) {
                int gc = colBase + wn * 64 + nt * 8 + q * 2;
                float v0 = acc[mt][nt][half * 2 + 0] + bias[gc];
                float v1 = acc[mt][nt][half * 2 + 1] + bias[gc + 1];
                float* cp = C + (long)gr * N + gc;
                if (mode == 1) {
                    float2 old = *(const float2*)cp;
                    v0 += old.x; v1 += old.y;
                } else if (mode == 2) {
                    v0 = rnd32(0.5f * v0 * (1.0f + erff(v0 * 0.70710678118654752f)));
                    v1 = rnd32(0.5f * v1 * (1.0f + erff(v1 * 0.70710678118654752f)));
                }
                *(float2*)cp = make_float2(v0, v1);
            }
        }
    }
}

// ---------------- attention pass 1: logits + exp + denom -----------------------
__global__ void k_att_logits(const int* __restrict__ ei, const float* __restrict__ qkv,
                             const float* __restrict__ degn, const float* __restrict__ wde,
                             float* __restrict__ exb, float* __restrict__ s) {
    int w = (blockIdx.x * blockDim.x + threadIdx.x) >> 5;
    int lane = threadIdx.x & 31;
    if (w >= NE) return;
    int src, dst;
    if (w < EE) { src = ei[w]; dst = ei[EE + w]; }
    else        { src = dst = w - EE; }
    float dnd = degn[dst], dns = degn[src];
    float4 q4 = *(const float4*)(qkv + (long)dst * 384 + lane * 4);
    float4 k4 = *(const float4*)(qkv + (long)src * 384 + 128 + lane * 4);
    const float4 wq = *(const float4*)(wde + lane * 4);
    const float4 wk = *(const float4*)(wde + 128 + lane * 4);
    q4.x += dnd * wq.x; q4.y += dnd * wq.y; q4.z += dnd * wq.z; q4.w += dnd * wq.w;
    k4.x += dns * wk.x; k4.y += dns * wk.y; k4.z += dns * wk.z; k4.w += dns * wk.w;
    float p = q4.x * k4.x + q4.y * k4.y + q4.z * k4.z + q4.w * k4.w;
    p += __shfl_xor_sync(0xffffffffu, p, 1);
    p += __shfl_xor_sync(0xffffffffu, p, 2);
    if ((lane & 3) == 0) {
        float att = p * 0.25f;
        att = fminf(fmaxf(att, -50.0f), 50.0f);
        float ex = __expf(att);
        int h = lane >> 2;
        exb[(long)w * HH + h] = ex;
        atomicAdd(&s[dst * HH + h], ex);
    }
}

// ---------------- attention pass 2: weighted aggregation -----------------------
__global__ void k_att_aggr(const int* __restrict__ ei, const float* __restrict__ qkv,
                           const float* __restrict__ degn, const float* __restrict__ wde,
                           const float* __restrict__ exb, const float* __restrict__ s,
                           float* __restrict__ aggr) {
    int w = (blockIdx.x * blockDim.x + threadIdx.x) >> 5;
    int lane = threadIdx.x & 31;
    if (w >= NE) return;
    int src, dst;
    if (w < EE) { src = ei[w]; dst = ei[EE + w]; }
    else        { src = dst = w - EE; }
    int h = lane >> 2;
    float alpha = exb[(long)w * HH + h] / (s[dst * HH + h] + 1e-16f);
    float dns = degn[src];
    float4 v4 = *(const float4*)(qkv + (long)src * 384 + 256 + lane * 4);
    const float4 wv = *(const float4*)(wde + 256 + lane * 4);
    v4.x += dns * wv.x; v4.y += dns * wv.y; v4.z += dns * wv.z; v4.w += dns * wv.w;
    float* dptr = aggr + (long)dst * DD + lane * 4;
    asm volatile("red.global.add.v4.f32 [%0], {%1,%2,%3,%4};"
                 :: "l"(dptr), "f"(v4.x * alpha), "f"(v4.y * alpha),
                    "f"(v4.z * alpha), "f"(v4.w * alpha) : "memory");
}

// ---------------- driver --------------------------------------------------------
extern "C" void kernel_launch(void* const* d_in, const int* in_sizes, int n_in,
                              void* d_out, int out_size) {
    const float* x    = (const float*)d_in[0];
    const int*   ei   = (const int*)d_in[1];
    const float* Wq   = (const float*)d_in[2];
    const float* Wk   = (const float*)d_in[3];
    const float* Wv   = (const float*)d_in[4];
    const float* Wo   = (const float*)d_in[5];
    const float* Wpos = (const float*)d_in[6];
    const float* Wdeg = (const float*)d_in[7];
    const float* W1   = (const float*)d_in[8];
    const float* W2   = (const float*)d_in[9];
    const float* bq   = (const float*)d_in[10];
    const float* bk   = (const float*)d_in[11];
    const float* bv   = (const float*)d_in[12];
    const float* bo   = (const float*)d_in[13];
    const float* bpos = (const float*)d_in[14];
    const float* bdeg = (const float*)d_in[15];
    const float* ln1b = (const float*)d_in[16];
    const float* ln2b = (const float*)d_in[17];
    const float* b1   = (const float*)d_in[18];
    const float* b2   = (const float*)d_in[19];
    const float* ln1g = (const float*)d_in[20];
    const float* ln2g = (const float*)d_in[21];
    float* xbuf = (float*)d_out;

    float *xn, *qkv, *aggr, *hb, *exb, *sb, *deg, *degn, *weff, *beff, *wde;
    float *wo, *w1, *w2;
    double* stats;
    cudaGetSymbolAddress((void**)&xn,    g_xn);
    cudaGetSymbolAddress((void**)&qkv,   g_qkv);
    cudaGetSymbolAddress((void**)&aggr,  g_aggr);
    cudaGetSymbolAddress((void**)&hb,    g_h);
    cudaGetSymbolAddress((void**)&exb,   g_ex);
    cudaGetSymbolAddress((void**)&sb,    g_s);
    cudaGetSymbolAddress((void**)&deg,   g_deg);
    cudaGetSymbolAddress((void**)&degn,  g_degn);
    cudaGetSymbolAddress((void**)&weff,  g_weff);
    cudaGetSymbolAddress((void**)&beff,  g_beff);
    cudaGetSymbolAddress((void**)&wde,   g_wdegeff);
    cudaGetSymbolAddress((void**)&wo,    g_wo);
    cudaGetSymbolAddress((void**)&w1,    g_w1);
    cudaGetSymbolAddress((void**)&w2,    g_w2);
    cudaGetSymbolAddress((void**)&stats, g_stats);

    cudaMemcpyAsync(xbuf, x, (size_t)NN * DD * sizeof(float), cudaMemcpyDeviceToDevice);

    const int rowBlocks  = (NN + BM - 1) / BM;
    const int lnBlocks   = (NN + 7) / 8;
    const int edgeBlocks = (NE + 7) / 8;

    // --- layer 0 head (order puts QKV GEMM at graph node 5 for ncu) ---
    k_weff<<<3 * DD, DD>>>(Wq, Wk, Wv, Wpos, Wdeg, bq, bk, bv, bpos, bdeg,
                           weff, beff, wde);
    k_layernorm<<<lnBlocks, 256>>>(xbuf, ln1g, ln1b, xn);
    k_prep<<<(NN * DD + 255) / 256, 256>>>(aggr, sb, deg, stats);
    gemm_tc<<<dim3(3 * DD / BN, rowBlocks), 256>>>(xn, weff, qkv, beff, NN, 3 * DD, DD, 0);
    k_deg_count<<<(EE + 255) / 256, 256>>>(ei, deg);
    k_deg_reduce<<<148, 256>>>(deg, stats);
    k_deg_norm<<<(NN + 255) / 256, 256>>>(deg, stats, degn);

    for (int l = 0; l < LL; l++) {
        k_att_logits<<<edgeBlocks, 256>>>(ei, qkv, degn, wde, exb, sb);
        k_att_aggr<<<edgeBlocks, 256>>>(ei, qkv, degn, wde, exb, sb, aggr);
        k_round_inplace<<<(NN * DD + 255) / 256, 256>>>(aggr, NN * DD);
        k_roundw<<<(DD * FFD + 255) / 256, 256>>>(Wo + (size_t)l * DD * DD,
                                                  W1 + (size_t)l * DD * FFD,
                                                  W2 + (size_t)l * FFD * DD, wo, w1, w2);
        gemm_tc<<<dim3(DD / BN, rowBlocks), 256>>>(aggr, wo, xbuf, bo + l * DD,
                                                   NN, DD, DD, 1);
        k_layernorm<<<lnBlocks, 256>>>(xbuf, ln2g + l * DD, ln2b + l * DD, xn);
        gemm_tc<<<dim3(FFD / BN, rowBlocks), 256>>>(xn, w1, hb, b1 + l * FFD,
                                                    NN, FFD, DD, 2);
        gemm_tc<<<dim3(DD / BN, rowBlocks), 256>>>(hb, w2, xbuf, b2 + l * DD,
                                                   NN, DD, FFD, 1);
        if (l + 1 < LL) {
            int n = l + 1;
            k_weff<<<3 * DD, DD>>>(Wq + (size_t)n * DD * DD, Wk + (size_t)n * DD * DD,
                                   Wv + (size_t)n * DD * DD, Wpos + (size_t)n * DD * DD,
                                   Wdeg + (size_t)n * DD,
                                   bq + n * DD, bk + n * DD, bv + n * DD,
                                   bpos + n * DD, bdeg + n * DD, weff, beff, wde);
            k_layernorm<<<lnBlocks, 256>>>(xbuf, ln1g + n * DD, ln1b + n * DD, xn);
            k_zero2<<<(NN * DD + 255) / 256, 256>>>(aggr, NN * DD, sb, NN * HH);
            gemm_tc<<<dim3(3 * DD / BN, rowBlocks), 256>>>(xn, weff, qkv, beff,
                                                           NN, 3 * DD, DD, 0);
        }
    }
}

// round 4
// speedup vs baseline: 2.1637x; 1.2249x over previous
#include <cuda_runtime.h>
#include <cuda_bf16.h>
#include <math.h>

#define NN 50000
#define EE 500000
#define DD 128
#define HH 8
#define LL 2
#define FFD 512
#define NE (EE + NN)

// ---------------- scratch ----------------------------------------------------
__device__ float  g_xn[NN * DD];
__device__ float  g_qkv[NN * 3 * DD];
__device__ float  g_aggr[NN * DD];
__device__ float  g_h[NN * FFD];
__device__ float  g_ex[NE * HH];
__device__ float  g_deg[NN];
__device__ float  g_degn[NN];
__device__ double g_stats[2];
__device__ float  g_weff[DD * 3 * DD];
__device__ float  g_beff[3 * DD];
__device__ float  g_wdegeff[3 * DD];
__device__ float  g_wo[DD * DD];
__device__ float  g_w1[DD * FFD];
__device__ float  g_w2[FFD * DD];
__device__ int    g_ddeg[NN];
__device__ int    g_off[NN + 1];
__device__ int    g_cur[NN];
__device__ int    g_csr[NE];

__device__ __forceinline__ unsigned f2tf32(float f) {
    unsigned r;
    asm("cvt.rna.tf32.f32 %0, %1;" : "=r"(r) : "f"(f));
    return r;
}
__device__ __forceinline__ float rnd32(float f) { return __uint_as_float(f2tf32(f)); }

// ---------------- prep --------------------------------------------------------
__global__ void k_prep(float* deg, int* ddeg, double* st) {
    int i = blockIdx.x * blockDim.x + threadIdx.x;
    if (i < NN) { deg[i] = 1.f; ddeg[i] = 1; }
    if (i == 0) { st[0] = 0.0; st[1] = 0.0; }
}

// ---------------- degree + CSR build -------------------------------------------
__global__ void k_degcount2(const int* __restrict__ ei, float* deg, int* ddeg) {
    int e = blockIdx.x * blockDim.x + threadIdx.x;
    if (e < EE) {
        atomicAdd(&deg[ei[e]], 1.0f);          // src degree (pos-enc)
        atomicAdd(&ddeg[ei[EE + e]], 1);       // dst degree (CSR)
    }
}
__global__ void k_scan(const int* __restrict__ ddeg, int* __restrict__ off) {
    __shared__ int wsum[32];
    __shared__ int carry;
    int t = threadIdx.x, lane = t & 31, wid = t >> 5;
    if (t == 0) { carry = 0; off[0] = 0; }
    __syncthreads();
    for (int base = 0; base < NN; base += 1024) {
        int i = base + t;
        int v = (i < NN) ? ddeg[i] : 0;
        int s = v;
        #pragma unroll
        for (int o = 1; o < 32; o <<= 1) {
            int u = __shfl_up_sync(0xffffffffu, s, o);
            if (lane >= o) s += u;
        }
        if (lane == 31) wsum[wid] = s;
        __syncthreads();
        if (wid == 0) {
            int ws = wsum[lane];
            #pragma unroll
            for (int o = 1; o < 32; o <<= 1) {
                int u = __shfl_up_sync(0xffffffffu, ws, o);
                if (lane >= o) ws += u;
            }
            wsum[lane] = ws;
        }
        __syncthreads();
        int add = (wid > 0) ? wsum[wid - 1] : 0;
        int incl = s + add + carry;
        if (i < NN) off[i + 1] = incl;
        __syncthreads();
        if (t == 1023) carry = incl;
        __syncthreads();
    }
}
__global__ void k_csr_self(const int* __restrict__ off, int* cur, int* csr) {
    int i = blockIdx.x * blockDim.x + threadIdx.x;
    if (i >= NN) return;
    int o = off[i];
    csr[o] = i;          // self loop first
    cur[i] = o + 1;
}
__global__ void k_csr_scatter(const int* __restrict__ ei, int* cur, int* csr) {
    int e = blockIdx.x * blockDim.x + threadIdx.x;
    if (e >= EE) return;
    int dst = ei[EE + e];
    int pos = atomicAdd(&cur[dst], 1);
    csr[pos] = ei[e];
}

__global__ void k_deg_reduce(const float* __restrict__ deg, double* st) {
    __shared__ double ss[256], sq[256];
    int t = threadIdx.x;
    double s = 0.0, q = 0.0;
    for (int i = blockIdx.x * blockDim.x + t; i < NN; i += gridDim.x * blockDim.x) {
        double d = (double)deg[i];
        s += d; q += d * d;
    }
    ss[t] = s; sq[t] = q;
    __syncthreads();
    for (int o = 128; o > 0; o >>= 1) {
        if (t < o) { ss[t] += ss[t + o]; sq[t] += sq[t + o]; }
        __syncthreads();
    }
    if (t == 0) { atomicAdd(&st[0], ss[0]); atomicAdd(&st[1], sq[0]); }
}
__global__ void k_deg_norm(const float* __restrict__ deg, const double* __restrict__ st,
                           float* __restrict__ degn) {
    int i = blockIdx.x * blockDim.x + threadIdx.x;
    if (i >= NN) return;
    double mean = st[0] / (double)NN;
    double var  = (st[1] - st[0] * st[0] / (double)NN) / (double)(NN - 1);
    float  sd   = (float)sqrt(var);
    degn[i] = (deg[i] - (float)mean) / (sd + 1e-6f);
}

// ---------------- folded effective weights (tf32-rounded output) --------------
__global__ void k_weff(const float* __restrict__ Wq, const float* __restrict__ Wk,
                       const float* __restrict__ Wv, const float* __restrict__ Wpos,
                       const float* __restrict__ Wdeg,
                       const float* __restrict__ bq, const float* __restrict__ bk,
                       const float* __restrict__ bv, const float* __restrict__ bpos,
                       const float* __restrict__ bdeg,
                       float* __restrict__ weff, float* __restrict__ beff,
                       float* __restrict__ wdegeff) {
    int j = blockIdx.x;
    int t = threadIdx.x;
    const float* W  = (j < DD) ? Wq : ((j < 2 * DD) ? Wk : Wv);
    const float* bb = (j < DD) ? bq : ((j < 2 * DD) ? bk : bv);
    int jj = j & (DD - 1);
    __shared__ float col[DD];
    col[t] = W[t * DD + jj];
    __syncthreads();
    float acc = col[t];
    #pragma unroll 8
    for (int m = 0; m < DD; m++) acc += Wpos[t * DD + m] * col[m];
    weff[t * (3 * DD) + j] = rnd32(acc);
    if (t == 0) {
        float s = 0.f;
        for (int m = 0; m < DD; m++) s += (bpos[m] + bdeg[m]) * col[m];
        beff[j] = s + bb[jj];
    }
    if (t == 1) {
        float s = 0.f;
        for (int m = 0; m < DD; m++) s += Wdeg[m] * col[m];
        wdegeff[j] = s;
    }
}

__global__ void k_roundw(const float* __restrict__ Wo, const float* __restrict__ W1,
                         const float* __restrict__ W2, float* wo, float* w1, float* w2) {
    int i = blockIdx.x * blockDim.x + threadIdx.x;
    if (i < DD * DD) wo[i] = rnd32(Wo[i]);
    if (i < DD * FFD) { w1[i] = rnd32(W1[i]); w2[i] = rnd32(W2[i]); }
}

// ---------------- LayerNorm (warp per node, tf32-rounded output) ---------------
__global__ void k_layernorm(const float* __restrict__ x, const float* __restrict__ g,
                            const float* __restrict__ b, float* __restrict__ out) {
    int node = (blockIdx.x * blockDim.x + threadIdx.x) >> 5;
    int lane = threadIdx.x & 31;
    if (node >= NN) return;
    const float4 v = *(const float4*)(x + (long)node * DD + lane * 4);
    float s = v.x + v.y + v.z + v.w;
    #pragma unroll
    for (int o = 16; o > 0; o >>= 1) s += __shfl_xor_sync(0xffffffffu, s, o);
    float mu = s * (1.0f / DD);
    float dx = v.x - mu, dy = v.y - mu, dz = v.z - mu, dw = v.w - mu;
    float q = dx * dx + dy * dy + dz * dz + dw * dw;
    #pragma unroll
    for (int o = 16; o > 0; o >>= 1) q += __shfl_xor_sync(0xffffffffu, q, o);
    float rs = rsqrtf(q * (1.0f / DD) + 1e-5f);
    const float4 gg = *(const float4*)(g + lane * 4);
    const float4 bb = *(const float4*)(b + lane * 4);
    float4 o4;
    o4.x = rnd32(dx * rs * gg.x + bb.x);
    o4.y = rnd32(dy * rs * gg.y + bb.y);
    o4.z = rnd32(dz * rs * gg.z + bb.z);
    o4.w = rnd32(dw * rs * gg.w + bb.w);
    *(float4*)(out + (long)node * DD + lane * 4) = o4;
}

// ---------------- pipelined tf32 tensor-core GEMM ------------------------------
#define BM 128
#define BN 128
#define BK 16
#define APAD 4
#define BPAD 8

__device__ __forceinline__ unsigned smemu32(const void* p) {
    return (unsigned)__cvta_generic_to_shared(p);
}

__global__ __launch_bounds__(256, 2) void gemm_tc(
    const float* __restrict__ A, const float* __restrict__ B, float* C,
    const float* __restrict__ bias, int M, int N, int K, int mode) {
    __shared__ float As[2][BM][BK + APAD];
    __shared__ float Bs[2][BK][BN + BPAD];

    const int tid  = threadIdx.x;
    const int warp = tid >> 5;
    const int lane = tid & 31;
    const int wm = warp >> 1;
    const int wn = warp & 1;
    const int g  = lane >> 2;
    const int q  = lane & 3;
    const int rowBase = blockIdx.y * BM;
    const int colBase = blockIdx.x * BN;

    float acc[2][8][4];
    #pragma unroll
    for (int i = 0; i < 2; i++)
        #pragma unroll
        for (int j = 0; j < 8; j++)
            #pragma unroll
            for (int k = 0; k < 4; k++) acc[i][j][k] = 0.0f;

    const int nk = K / BK;

    auto loadA = [&](int s, int k0) {
        #pragma unroll
        for (int i = 0; i < 2; i++) {
            int idx = tid + i * 256;
            int r = idx >> 2, c = (idx & 3) * 4;
            int grow = rowBase + r;
            const float* src = A + (long)(grow < M ? grow : M - 1) * K + k0 + c;
            int sz = (grow < M) ? 16 : 0;
            asm volatile("cp.async.cg.shared.global [%0], [%1], 16, %2;"
                         :: "r"(smemu32(&As[s][r][c])), "l"(src), "r"(sz));
        }
    };
    auto loadB = [&](int s, int k0) {
        #pragma unroll
        for (int i = 0; i < 2; i++) {
            int idx = tid + i * 256;
            int r = idx >> 5, c = (idx & 31) * 4;
            const float* src = B + (long)(k0 + r) * N + colBase + c;
            asm volatile("cp.async.cg.shared.global [%0], [%1], 16;"
                         :: "r"(smemu32(&Bs[s][r][c])), "l"(src));
        }
    };

    loadA(0, 0); loadB(0, 0);
    asm volatile("cp.async.commit_group;");

    for (int kb = 0; kb < nk; kb++) {
        int buf = kb & 1;
        if (kb + 1 < nk) {
            loadA(buf ^ 1, (kb + 1) * BK);
            loadB(buf ^ 1, (kb + 1) * BK);
            asm volatile("cp.async.commit_group;");
            asm volatile("cp.async.wait_group 1;");
        } else {
            asm volatile("cp.async.wait_group 0;");
        }
        __syncthreads();

        #pragma unroll
        for (int kk = 0; kk < BK; kk += 8) {
            unsigned a_frag[2][4];
            #pragma unroll
            for (int mt = 0; mt < 2; mt++) {
                int row = wm * 32 + mt * 16 + g;
                a_frag[mt][0] = __float_as_uint(As[buf][row][kk + q]);
                a_frag[mt][1] = __float_as_uint(As[buf][row + 8][kk + q]);
                a_frag[mt][2] = __float_as_uint(As[buf][row][kk + q + 4]);
                a_frag[mt][3] = __float_as_uint(As[buf][row + 8][kk + q + 4]);
            }
            unsigned b_frag[8][2];
            #pragma unroll
            for (int nt = 0; nt < 8; nt++) {
                int col = wn * 64 + nt * 8 + g;
                b_frag[nt][0] = __float_as_uint(Bs[buf][kk + q][col]);
                b_frag[nt][1] = __float_as_uint(Bs[buf][kk + q + 4][col]);
            }
            #pragma unroll
            for (int mt = 0; mt < 2; mt++)
                #pragma unroll
                for (int nt = 0; nt < 8; nt++) {
                    asm volatile(
                        "mma.sync.aligned.m16n8k8.row.col.f32.tf32.tf32.f32 "
                        "{%0,%1,%2,%3}, {%4,%5,%6,%7}, {%8,%9}, {%0,%1,%2,%3};"
                        : "+f"(acc[mt][nt][0]), "+f"(acc[mt][nt][1]),
                          "+f"(acc[mt][nt][2]), "+f"(acc[mt][nt][3])
                        : "r"(a_frag[mt][0]), "r"(a_frag[mt][1]),
                          "r"(a_frag[mt][2]), "r"(a_frag[mt][3]),
                          "r"(b_frag[nt][0]), "r"(b_frag[nt][1]));
                }
        }
        __syncthreads();
    }

    #pragma unroll
    for (int mt = 0; mt < 2; mt++) {
        #pragma unroll
        for (int half = 0; half < 2; half++) {
            int gr = rowBase + wm * 32 + mt * 16 + g + half * 8;
            if (gr >= M) continue;
            #pragma unroll
            for (int nt = 0; nt < 8; nt++) {
                int gc = colBase + wn * 64 + nt * 8 + q * 2;
                float v0 = acc[mt][nt][half * 2 + 0] + bias[gc];
                float v1 = acc[mt][nt][half * 2 + 1] + bias[gc + 1];
                float* cp = C + (long)gr * N + gc;
                if (mode == 1) {
                    float2 old = *(const float2*)cp;
                    v0 += old.x; v1 += old.y;
                } else if (mode == 2) {
                    v0 = rnd32(0.5f * v0 * (1.0f + erff(v0 * 0.70710678118654752f)));
                    v1 = rnd32(0.5f * v1 * (1.0f + erff(v1 * 0.70710678118654752f)));
                }
                *(float2*)cp = make_float2(v0, v1);
            }
        }
    }
}

// ---------------- fused CSR attention (warp per dst node) ----------------------
__global__ __launch_bounds__(256) void k_attn(
    const int* __restrict__ off, const int* __restrict__ csr,
    const float* __restrict__ qkv, const float* __restrict__ degn,
    const float* __restrict__ wde, float* __restrict__ exb,
    float* __restrict__ aggr) {
    int w = (blockIdx.x * blockDim.x + threadIdx.x) >> 5;
    int lane = threadIdx.x & 31;
    if (w >= NN) return;
    const int h = lane >> 2;
    const int beg = off[w], end = off[w + 1];

    const float4 wq = *(const float4*)(wde + lane * 4);
    const float4 wk = *(const float4*)(wde + 128 + lane * 4);
    const float4 wv = *(const float4*)(wde + 256 + lane * 4);

    float dnd = degn[w];
    float4 qv = *(const float4*)(qkv + (long)w * 384 + lane * 4);
    qv.x += dnd * wq.x; qv.y += dnd * wq.y; qv.z += dnd * wq.z; qv.w += dnd * wq.w;

    // ---- pass 1: exp(logits) + denominator in registers ----
    float s_acc = 0.0f;
    int e = beg;
    for (; e + 1 < end; e += 2) {
        int s0 = csr[e], s1 = csr[e + 1];
        float d0 = degn[s0], d1 = degn[s1];
        float4 k0 = *(const float4*)(qkv + (long)s0 * 384 + 128 + lane * 4);
        float4 k1 = *(const float4*)(qkv + (long)s1 * 384 + 128 + lane * 4);
        float p0 = qv.x * (k0.x + d0 * wk.x) + qv.y * (k0.y + d0 * wk.y)
                 + qv.z * (k0.z + d0 * wk.z) + qv.w * (k0.w + d0 * wk.w);
        float p1 = qv.x * (k1.x + d1 * wk.x) + qv.y * (k1.y + d1 * wk.y)
                 + qv.z * (k1.z + d1 * wk.z) + qv.w * (k1.w + d1 * wk.w);
        p0 += __shfl_xor_sync(0xffffffffu, p0, 1);
        p0 += __shfl_xor_sync(0xffffffffu, p0, 2);
        p1 += __shfl_xor_sync(0xffffffffu, p1, 1);
        p1 += __shfl_xor_sync(0xffffffffu, p1, 2);
        float ex0 = __expf(fminf(fmaxf(p0 * 0.25f, -50.f), 50.f));
        float ex1 = __expf(fminf(fmaxf(p1 * 0.25f, -50.f), 50.f));
        s_acc += ex0 + ex1;
        if ((lane & 3) == 0) {
            exb[(long)e * HH + h] = ex0;
            exb[(long)(e + 1) * HH + h] = ex1;
        }
    }
    if (e < end) {
        int s0 = csr[e];
        float d0 = degn[s0];
        float4 k0 = *(const float4*)(qkv + (long)s0 * 384 + 128 + lane * 4);
        float p0 = qv.x * (k0.x + d0 * wk.x) + qv.y * (k0.y + d0 * wk.y)
                 + qv.z * (k0.z + d0 * wk.z) + qv.w * (k0.w + d0 * wk.w);
        p0 += __shfl_xor_sync(0xffffffffu, p0, 1);
        p0 += __shfl_xor_sync(0xffffffffu, p0, 2);
        float ex0 = __expf(fminf(fmaxf(p0 * 0.25f, -50.f), 50.f));
        s_acc += ex0;
        if ((lane & 3) == 0) exb[(long)e * HH + h] = ex0;
    }
    float rs = 1.0f / (s_acc + 1e-16f);

    // ---- pass 2: alpha-weighted V aggregation in registers ----
    float ax = 0.f, ay = 0.f, az = 0.f, aw = 0.f;
    e = beg;
    for (; e + 1 < end; e += 2) {
        int s0 = csr[e], s1 = csr[e + 1];
        float a0 = exb[(long)e * HH + h] * rs;
        float a1 = exb[(long)(e + 1) * HH + h] * rs;
        float d0 = degn[s0], d1 = degn[s1];
        float4 v0 = *(const float4*)(qkv + (long)s0 * 384 + 256 + lane * 4);
        float4 v1 = *(const float4*)(qkv + (long)s1 * 384 + 256 + lane * 4);
        ax += a0 * (v0.x + d0 * wv.x) + a1 * (v1.x + d1 * wv.x);
        ay += a0 * (v0.y + d0 * wv.y) + a1 * (v1.y + d1 * wv.y);
        az += a0 * (v0.z + d0 * wv.z) + a1 * (v1.z + d1 * wv.z);
        aw += a0 * (v0.w + d0 * wv.w) + a1 * (v1.w + d1 * wv.w);
    }
    if (e < end) {
        int s0 = csr[e];
        float a0 = exb[(long)e * HH + h] * rs;
        float d0 = degn[s0];
        float4 v0 = *(const float4*)(qkv + (long)s0 * 384 + 256 + lane * 4);
        ax += a0 * (v0.x + d0 * wv.x);
        ay += a0 * (v0.y + d0 * wv.y);
        az += a0 * (v0.z + d0 * wv.z);
        aw += a0 * (v0.w + d0 * wv.w);
    }
    float4 o4;
    o4.x = rnd32(ax); o4.y = rnd32(ay); o4.z = rnd32(az); o4.w = rnd32(aw);
    *(float4*)(aggr + (long)w * DD + lane * 4) = o4;
}

// ---------------- driver --------------------------------------------------------
extern "C" void kernel_launch(void* const* d_in, const int* in_sizes, int n_in,
                              void* d_out, int out_size) {
    const float* x    = (const float*)d_in[0];
    const int*   ei   = (const int*)d_in[1];
    const float* Wq   = (const float*)d_in[2];
    const float* Wk   = (const float*)d_in[3];
    const float* Wv   = (const float*)d_in[4];
    const float* Wo   = (const float*)d_in[5];
    const float* Wpos = (const float*)d_in[6];
    const float* Wdeg = (const float*)d_in[7];
    const float* W1   = (const float*)d_in[8];
    const float* W2   = (const float*)d_in[9];
    const float* bq   = (const float*)d_in[10];
    const float* bk   = (const float*)d_in[11];
    const float* bv   = (const float*)d_in[12];
    const float* bo   = (const float*)d_in[13];
    const float* bpos = (const float*)d_in[14];
    const float* bdeg = (const float*)d_in[15];
    const float* ln1b = (const float*)d_in[16];
    const float* ln2b = (const float*)d_in[17];
    const float* b1   = (const float*)d_in[18];
    const float* b2   = (const float*)d_in[19];
    const float* ln1g = (const float*)d_in[20];
    const float* ln2g = (const float*)d_in[21];
    float* xbuf = (float*)d_out;

    float *xn, *qkv, *aggr, *hb, *exb, *deg, *degn, *weff, *beff, *wde;
    float *wo, *w1, *w2;
    int *ddeg, *off, *cur, *csr;
    double* stats;
    cudaGetSymbolAddress((void**)&xn,    g_xn);
    cudaGetSymbolAddress((void**)&qkv,   g_qkv);
    cudaGetSymbolAddress((void**)&aggr,  g_aggr);
    cudaGetSymbolAddress((void**)&hb,    g_h);
    cudaGetSymbolAddress((void**)&exb,   g_ex);
    cudaGetSymbolAddress((void**)&deg,   g_deg);
    cudaGetSymbolAddress((void**)&degn,  g_degn);
    cudaGetSymbolAddress((void**)&weff,  g_weff);
    cudaGetSymbolAddress((void**)&beff,  g_beff);
    cudaGetSymbolAddress((void**)&wde,   g_wdegeff);
    cudaGetSymbolAddress((void**)&wo,    g_wo);
    cudaGetSymbolAddress((void**)&w1,    g_w1);
    cudaGetSymbolAddress((void**)&w2,    g_w2);
    cudaGetSymbolAddress((void**)&ddeg,  g_ddeg);
    cudaGetSymbolAddress((void**)&off,   g_off);
    cudaGetSymbolAddress((void**)&cur,   g_cur);
    cudaGetSymbolAddress((void**)&csr,   g_csr);
    cudaGetSymbolAddress((void**)&stats, g_stats);

    cudaMemcpyAsync(xbuf, x, (size_t)NN * DD * sizeof(float), cudaMemcpyDeviceToDevice);

    const int rowBlocks = (NN + BM - 1) / BM;
    const int lnBlocks  = (NN + 7) / 8;
    const int nodeWarpBlocks = (NN + 7) / 8;   // 8 warps per block, warp per node

    // prefix kept identical so ncu (-s 5 -c 1) keeps landing on the QKV GEMM
    k_weff<<<3 * DD, DD>>>(Wq, Wk, Wv, Wpos, Wdeg, bq, bk, bv, bpos, bdeg,
                           weff, beff, wde);
    k_layernorm<<<lnBlocks, 256>>>(xbuf, ln1g, ln1b, xn);
    k_prep<<<(NN + 255) / 256, 256>>>(deg, ddeg, stats);
    gemm_tc<<<dim3(3 * DD / BN, rowBlocks), 256>>>(xn, weff, qkv, beff, NN, 3 * DD, DD, 0);

    // degree stats + CSR build (once; edge_index is launch-invariant)
    k_degcount2<<<(EE + 255) / 256, 256>>>(ei, deg, ddeg);
    k_scan<<<1, 1024>>>(ddeg, off);
    k_deg_reduce<<<148, 256>>>(deg, stats);
    k_deg_norm<<<(NN + 255) / 256, 256>>>(deg, stats, degn);
    k_csr_self<<<(NN + 255) / 256, 256>>>(off, cur, csr);
    k_csr_scatter<<<(EE + 255) / 256, 256>>>(ei, cur, csr);

    for (int l = 0; l < LL; l++) {
        k_attn<<<nodeWarpBlocks, 256>>>(off, csr, qkv, degn, wde, exb, aggr);
        k_roundw<<<(DD * FFD + 255) / 256, 256>>>(Wo + (size_t)l * DD * DD,
                                                  W1 + (size_t)l * DD * FFD,
                                                  W2 + (size_t)l * FFD * DD, wo, w1, w2);
        gemm_tc<<<dim3(DD / BN, rowBlocks), 256>>>(aggr, wo, xbuf, bo + l * DD,
                                                   NN, DD, DD, 1);
        k_layernorm<<<lnBlocks, 256>>>(xbuf, ln2g + l * DD, ln2b + l * DD, xn);
        gemm_tc<<<dim3(FFD / BN, rowBlocks), 256>>>(xn, w1, hb, b1 + l * FFD,
                                                    NN, FFD, DD, 2);
        gemm_tc<<<dim3(DD / BN, rowBlocks), 256>>>(hb, w2, xbuf, b2 + l * DD,
                                                   NN, DD, FFD, 1);
        if (l + 1 < LL) {
            int n = l + 1;
            k_weff<<<3 * DD, DD>>>(Wq + (size_t)n * DD * DD, Wk + (size_t)n * DD * DD,
                                   Wv + (size_t)n * DD * DD, Wpos + (size_t)n * DD * DD,
                                   Wdeg + (size_t)n * DD,
                                   bq + n * DD, bk + n * DD, bv + n * DD,
                                   bpos + n * DD, bdeg + n * DD, weff, beff, wde);
            k_layernorm<<<lnBlocks, 256>>>(xbuf, ln1g + n * DD, ln1b + n * DD, xn);
            gemm_tc<<<dim3(3 * DD / BN, rowBlocks), 256>>>(xn, weff, qkv, beff,
                                                           NN, 3 * DD, DD, 0);
        }
    }
}

// round 5
// speedup vs baseline: 2.2718x; 1.0500x over previous
#include <cuda_runtime.h>
#include <cuda_bf16.h>
#include <math.h>

#define NN 50000
#define EE 500000
#define DD 128
#define HH 8
#define LL 2
#define FFD 512
#define NE (EE + NN)

// ---------------- scratch ----------------------------------------------------
__device__ float  g_xn[NN * DD];
__device__ float  g_qkv[NN * 3 * DD];
__device__ float  g_aggr[NN * DD];
__device__ float  g_h[NN * FFD];
__device__ float  g_ex[NE * HH];
__device__ float  g_deg[NN];
__device__ float  g_degn[NN];
__device__ double g_stats[2];
__device__ float  g_weff[3 * DD * DD];    // transposed [N=384][K=128]
__device__ float  g_beff[3 * DD];
__device__ float  g_wdegeff[3 * DD];
__device__ float  g_wo[DD * DD];          // transposed [N][K]
__device__ float  g_w1[FFD * DD];         // transposed [512][128]
__device__ float  g_w2[DD * FFD];         // transposed [128][512]
__device__ int    g_ddeg[NN];
__device__ int    g_off[NN + 1];
__device__ int    g_cur[NN];
__device__ int    g_csr[NE];

__device__ __forceinline__ unsigned f2tf32(float f) {
    unsigned r;
    asm("cvt.rna.tf32.f32 %0, %1;" : "=r"(r) : "f"(f));
    return r;
}
__device__ __forceinline__ float rnd32(float f) { return __uint_as_float(f2tf32(f)); }

// ---------------- prep --------------------------------------------------------
__global__ void k_prep(float* deg, int* ddeg, double* st) {
    int i = blockIdx.x * blockDim.x + threadIdx.x;
    if (i < NN) { deg[i] = 1.f; ddeg[i] = 1; }
    if (i == 0) { st[0] = 0.0; st[1] = 0.0; }
}

// ---------------- degree + CSR build -------------------------------------------
__global__ void k_degcount2(const int* __restrict__ ei, float* deg, int* ddeg) {
    int e = blockIdx.x * blockDim.x + threadIdx.x;
    if (e < EE) {
        atomicAdd(&deg[ei[e]], 1.0f);
        atomicAdd(&ddeg[ei[EE + e]], 1);
    }
}
__global__ void k_scan(const int* __restrict__ ddeg, int* __restrict__ off) {
    __shared__ int wsum[32];
    __shared__ int carry;
    int t = threadIdx.x, lane = t & 31, wid = t >> 5;
    if (t == 0) { carry = 0; off[0] = 0; }
    __syncthreads();
    for (int base = 0; base < NN; base += 1024) {
        int i = base + t;
        int v = (i < NN) ? ddeg[i] : 0;
        int s = v;
        #pragma unroll
        for (int o = 1; o < 32; o <<= 1) {
            int u = __shfl_up_sync(0xffffffffu, s, o);
            if (lane >= o) s += u;
        }
        if (lane == 31) wsum[wid] = s;
        __syncthreads();
        if (wid == 0) {
            int ws = wsum[lane];
            #pragma unroll
            for (int o = 1; o < 32; o <<= 1) {
                int u = __shfl_up_sync(0xffffffffu, ws, o);
                if (lane >= o) ws += u;
            }
            wsum[lane] = ws;
        }
        __syncthreads();
        int add = (wid > 0) ? wsum[wid - 1] : 0;
        int incl = s + add + carry;
        if (i < NN) off[i + 1] = incl;
        __syncthreads();
        if (t == 1023) carry = incl;
        __syncthreads();
    }
}
__global__ void k_csr_self(const int* __restrict__ off, int* cur, int* csr) {
    int i = blockIdx.x * blockDim.x + threadIdx.x;
    if (i >= NN) return;
    int o = off[i];
    csr[o] = i;
    cur[i] = o + 1;
}
__global__ void k_csr_scatter(const int* __restrict__ ei, int* cur, int* csr) {
    int e = blockIdx.x * blockDim.x + threadIdx.x;
    if (e >= EE) return;
    int dst = ei[EE + e];
    int pos = atomicAdd(&cur[dst], 1);
    csr[pos] = ei[e];
}

__global__ void k_deg_reduce(const float* __restrict__ deg, double* st) {
    __shared__ double ss[256], sq[256];
    int t = threadIdx.x;
    double s = 0.0, q = 0.0;
    for (int i = blockIdx.x * blockDim.x + t; i < NN; i += gridDim.x * blockDim.x) {
        double d = (double)deg[i];
        s += d; q += d * d;
    }
    ss[t] = s; sq[t] = q;
    __syncthreads();
    for (int o = 128; o > 0; o >>= 1) {
        if (t < o) { ss[t] += ss[t + o]; sq[t] += sq[t + o]; }
        __syncthreads();
    }
    if (t == 0) { atomicAdd(&st[0], ss[0]); atomicAdd(&st[1], sq[0]); }
}
__global__ void k_deg_norm(const float* __restrict__ deg, const double* __restrict__ st,
                           float* __restrict__ degn) {
    int i = blockIdx.x * blockDim.x + threadIdx.x;
    if (i >= NN) return;
    double mean = st[0] / (double)NN;
    double var  = (st[1] - st[0] * st[0] / (double)NN) / (double)(NN - 1);
    float  sd   = (float)sqrt(var);
    degn[i] = (deg[i] - (float)mean) / (sd + 1e-6f);
}

// ---------------- folded effective weights (tf32-rounded, TRANSPOSED [N][K]) ---
__global__ void k_weff(const float* __restrict__ Wq, const float* __restrict__ Wk,
                       const float* __restrict__ Wv, const float* __restrict__ Wpos,
                       const float* __restrict__ Wdeg,
                       const float* __restrict__ bq, const float* __restrict__ bk,
                       const float* __restrict__ bv, const float* __restrict__ bpos,
                       const float* __restrict__ bdeg,
                       float* __restrict__ weff, float* __restrict__ beff,
                       float* __restrict__ wdegeff) {
    int j = blockIdx.x;              // output col (n) 0..383
    int t = threadIdx.x;             // k 0..127
    const float* W  = (j < DD) ? Wq : ((j < 2 * DD) ? Wk : Wv);
    const float* bb = (j < DD) ? bq : ((j < 2 * DD) ? bk : bv);
    int jj = j & (DD - 1);
    __shared__ float col[DD];
    col[t] = W[t * DD + jj];
    __syncthreads();
    float acc = col[t];
    #pragma unroll 8
    for (int m = 0; m < DD; m++) acc += Wpos[t * DD + m] * col[m];
    weff[j * DD + t] = rnd32(acc);   // transposed store
    if (t == 0) {
        float s = 0.f;
        for (int m = 0; m < DD; m++) s += (bpos[m] + bdeg[m]) * col[m];
        beff[j] = s + bb[jj];
    }
    if (t == 1) {
        float s = 0.f;
        for (int m = 0; m < DD; m++) s += Wdeg[m] * col[m];
        wdegeff[j] = s;
    }
}

// round + transpose weights to [N][K]
__global__ void k_roundw(const float* __restrict__ Wo, const float* __restrict__ W1,
                         const float* __restrict__ W2, float* wo, float* w1, float* w2) {
    int i = blockIdx.x * blockDim.x + threadIdx.x;
    if (i < DD * DD) {
        int k = i / DD, n = i % DD;
        wo[n * DD + k] = rnd32(Wo[i]);          // Wo [128][128]
    }
    if (i < DD * FFD) {
        int k1 = i / FFD, n1 = i % FFD;
        w1[n1 * DD + k1] = rnd32(W1[i]);        // W1 [128][512] -> [512][128]
        int k2 = i / DD, n2 = i % DD;
        w2[n2 * FFD + k2] = rnd32(W2[i]);       // W2 [512][128] -> [128][512]
    }
}

// ---------------- LayerNorm (warp per node, tf32-rounded output) ---------------
__global__ void k_layernorm(const float* __restrict__ x, const float* __restrict__ g,
                            const float* __restrict__ b, float* __restrict__ out) {
    int node = (blockIdx.x * blockDim.x + threadIdx.x) >> 5;
    int lane = threadIdx.x & 31;
    if (node >= NN) return;
    const float4 v = *(const float4*)(x + (long)node * DD + lane * 4);
    float s = v.x + v.y + v.z + v.w;
    #pragma unroll
    for (int o = 16; o > 0; o >>= 1) s += __shfl_xor_sync(0xffffffffu, s, o);
    float mu = s * (1.0f / DD);
    float dx = v.x - mu, dy = v.y - mu, dz = v.z - mu, dw = v.w - mu;
    float q = dx * dx + dy * dy + dz * dz + dw * dw;
    #pragma unroll
    for (int o = 16; o > 0; o >>= 1) q += __shfl_xor_sync(0xffffffffu, q, o);
    float rs = rsqrtf(q * (1.0f / DD) + 1e-5f);
    const float4 gg = *(const float4*)(g + lane * 4);
    const float4 bb = *(const float4*)(b + lane * 4);
    float4 o4;
    o4.x = rnd32(dx * rs * gg.x + bb.x);
    o4.y = rnd32(dy * rs * gg.y + bb.y);
    o4.z = rnd32(dz * rs * gg.z + bb.z);
    o4.w = rnd32(dw * rs * gg.w + bb.w);
    *(float4*)(out + (long)node * DD + lane * 4) = o4;
}

// ---------------- 3-stage pipelined tf32 GEMM with ldmatrix fragments ----------
// C[M,N] = A[M,K] @ Bt[N,K]^T (+epilogue). Operands pre-rounded to tf32.
// mode 0: + bias   mode 1: + bias + C   mode 2: round(gelu(+bias))
#define BM 128
#define BN 128
#define BK 16
#define LDP 20                 // row stride in floats (bank-conflict free)
#define NSTAGE 3
#define STAGE_F (BM * LDP)     // floats per A (or B) stage

__device__ __forceinline__ unsigned smemu32(const void* p) {
    return (unsigned)__cvta_generic_to_shared(p);
}

__global__ __launch_bounds__(256, 2) void gemm_tc(
    const float* __restrict__ A, const float* __restrict__ Bt, float* C,
    const float* __restrict__ bias, int M, int N, int K, int mode) {
    extern __shared__ float sm[];
    float* As = sm;                          // [NSTAGE][BM][LDP]
    float* Bs = sm + NSTAGE * STAGE_F;       // [NSTAGE][BN][LDP]

    const int tid  = threadIdx.x;
    const int warp = tid >> 5;
    const int lane = tid & 31;
    const int wm = warp >> 1;
    const int wn = warp & 1;
    const int g  = lane >> 2;
    const int q  = lane & 3;
    const int rowBase = blockIdx.y * BM;
    const int colBase = blockIdx.x * BN;

    float acc[2][8][4];
    #pragma unroll
    for (int i = 0; i < 2; i++)
        #pragma unroll
        for (int j = 0; j < 8; j++)
            #pragma unroll
            for (int k = 0; k < 4; k++) acc[i][j][k] = 0.0f;

    const int nk = K / BK;

    auto loadA = [&](int s, int k0) {
        #pragma unroll
        for (int i = 0; i < 2; i++) {
            int idx = tid + i * 256;
            int r = idx >> 2, c = (idx & 3) * 4;
            int grow = rowBase + r;
            const float* src = A + (long)(grow < M ? grow : M - 1) * K + k0 + c;
            int sz = (grow < M) ? 16 : 0;
            asm volatile("cp.async.cg.shared.global [%0], [%1], 16, %2;"
                         :: "r"(smemu32(As + s * STAGE_F + r * LDP + c)), "l"(src), "r"(sz));
        }
    };
    auto loadB = [&](int s, int k0) {
        #pragma unroll
        for (int i = 0; i < 2; i++) {
            int idx = tid + i * 256;
            int n = idx >> 2, c = (idx & 3) * 4;
            const float* src = Bt + (long)(colBase + n) * K + k0 + c;
            asm volatile("cp.async.cg.shared.global [%0], [%1], 16;"
                         :: "r"(smemu32(Bs + s * STAGE_F + n * LDP + c)), "l"(src));
        }
    };

    // ldmatrix per-thread byte offsets within a stage
    unsigned aBase = smemu32(As);
    unsigned bBase = smemu32(Bs);
    unsigned offA[2], offB[4];
    #pragma unroll
    for (int mt = 0; mt < 2; mt++) {
        int row = wm * 32 + mt * 16 + (lane & 15);
        int kc  = (lane >> 4) << 2;
        offA[mt] = (unsigned)((row * LDP + kc) * 4);
    }
    #pragma unroll
    for (int p = 0; p < 4; p++) {
        int row = wn * 64 + p * 16 + ((lane >> 4) << 3) + (lane & 7);
        int kc  = ((lane >> 3) & 1) << 2;
        offB[p] = (unsigned)((row * LDP + kc) * 4);
    }
    const unsigned stageBytes = STAGE_F * 4;

    loadA(0, 0); loadB(0, 0);
    asm volatile("cp.async.commit_group;");
    if (nk > 1) { loadA(1, BK); loadB(1, BK); }
    asm volatile("cp.async.commit_group;");

    int buf = 0;
    for (int kb = 0; kb < nk; kb++) {
        asm volatile("cp.async.wait_group 1;");
        __syncthreads();
        if (kb + 2 < nk) {
            int s = (kb + 2) % NSTAGE;
            loadA(s, (kb + 2) * BK);
            loadB(s, (kb + 2) * BK);
        }
        asm volatile("cp.async.commit_group;");

        unsigned aStage = aBase + buf * stageBytes;
        unsigned bStage = bBase + buf * stageBytes;
        #pragma unroll
        for (int kk = 0; kk < BK; kk += 8) {
            unsigned a_frag[2][4];
            #pragma unroll
            for (int mt = 0; mt < 2; mt++) {
                asm volatile("ldmatrix.sync.aligned.m8n8.x4.shared.b16 "
                             "{%0,%1,%2,%3}, [%4];"
                             : "=r"(a_frag[mt][0]), "=r"(a_frag[mt][1]),
                               "=r"(a_frag[mt][2]), "=r"(a_frag[mt][3])
                             : "r"(aStage + offA[mt] + kk * 4));
            }
            unsigned b_frag[8][2];
            #pragma unroll
            for (int p = 0; p < 4; p++) {
                asm volatile("ldmatrix.sync.aligned.m8n8.x4.shared.b16 "
                             "{%0,%1,%2,%3}, [%4];"
                             : "=r"(b_frag[2 * p][0]), "=r"(b_frag[2 * p][1]),
                               "=r"(b_frag[2 * p + 1][0]), "=r"(b_frag[2 * p + 1][1])
                             : "r"(bStage + offB[p] + kk * 4));
            }
            #pragma unroll
            for (int mt = 0; mt < 2; mt++)
                #pragma unroll
                for (int nt = 0; nt < 8; nt++) {
                    asm volatile(
                        "mma.sync.aligned.m16n8k8.row.col.f32.tf32.tf32.f32 "
                        "{%0,%1,%2,%3}, {%4,%5,%6,%7}, {%8,%9}, {%0,%1,%2,%3};"
                        : "+f"(acc[mt][nt][0]), "+f"(acc[mt][nt][1]),
                          "+f"(acc[mt][nt][2]), "+f"(acc[mt][nt][3])
                        : "r"(a_frag[mt][0]), "r"(a_frag[mt][1]),
                          "r"(a_frag[mt][2]), "r"(a_frag[mt][3]),
                          "r"(b_frag[nt][0]), "r"(b_frag[nt][1]));
                }
        }
        __syncthreads();
        buf = (buf + 1 == NSTAGE) ? 0 : buf + 1;
    }

    #pragma unroll
    for (int mt = 0; mt < 2; mt++) {
        #pragma unroll
        for (int half = 0; half < 2; half++) {
            int gr = rowBase + wm * 32 + mt * 16 + g + half * 8;
            if (gr >= M) continue;
            #pragma unroll
            for (int nt = 0; nt < 8; nt++) {
                int gc = colBase + wn * 64 + nt * 8 + q * 2;
                float v0 = acc[mt][nt][half * 2 + 0] + bias[gc];
                float v1 = acc[mt][nt][half * 2 + 1] + bias[gc + 1];
                float* cp = C + (long)gr * N + gc;
                if (mode == 1) {
                    float2 old = *(const float2*)cp;
                    v0 += old.x; v1 += old.y;
                } else if (mode == 2) {
                    v0 = rnd32(0.5f * v0 * (1.0f + erff(v0 * 0.70710678118654752f)));
                    v1 = rnd32(0.5f * v1 * (1.0f + erff(v1 * 0.70710678118654752f)));
                }
                *(float2*)cp = make_float2(v0, v1);
            }
        }
    }
}
#define GEMM_SMEM (NSTAGE * STAGE_F * 2 * (int)sizeof(float))

// ---------------- fused CSR attention (warp per dst node) ----------------------
__global__ __launch_bounds__(256) void k_attn(
    const int* __restrict__ off, const int* __restrict__ csr,
    const float* __restrict__ qkv, const float* __restrict__ degn,
    const float* __restrict__ wde, float* __restrict__ exb,
    float* __restrict__ aggr) {
    int w = (blockIdx.x * blockDim.x + threadIdx.x) >> 5;
    int lane = threadIdx.x & 31;
    if (w >= NN) return;
    const int h = lane >> 2;
    const int beg = off[w], end = off[w + 1];

    const float4 wq = *(const float4*)(wde + lane * 4);
    const float4 wk = *(const float4*)(wde + 128 + lane * 4);
    const float4 wv = *(const float4*)(wde + 256 + lane * 4);

    float dnd = degn[w];
    float4 qv = *(const float4*)(qkv + (long)w * 384 + lane * 4);
    qv.x += dnd * wq.x; qv.y += dnd * wq.y; qv.z += dnd * wq.z; qv.w += dnd * wq.w;

    float s_acc = 0.0f;
    int e = beg;
    for (; e + 1 < end; e += 2) {
        int s0 = csr[e], s1 = csr[e + 1];
        float d0 = degn[s0], d1 = degn[s1];
        float4 k0 = *(const float4*)(qkv + (long)s0 * 384 + 128 + lane * 4);
        float4 k1 = *(const float4*)(qkv + (long)s1 * 384 + 128 + lane * 4);
        float p0 = qv.x * (k0.x + d0 * wk.x) + qv.y * (k0.y + d0 * wk.y)
                 + qv.z * (k0.z + d0 * wk.z) + qv.w * (k0.w + d0 * wk.w);
        float p1 = qv.x * (k1.x + d1 * wk.x) + qv.y * (k1.y + d1 * wk.y)
                 + qv.z * (k1.z + d1 * wk.z) + qv.w * (k1.w + d1 * wk.w);
        p0 += __shfl_xor_sync(0xffffffffu, p0, 1);
        p0 += __shfl_xor_sync(0xffffffffu, p0, 2);
        p1 += __shfl_xor_sync(0xffffffffu, p1, 1);
        p1 += __shfl_xor_sync(0xffffffffu, p1, 2);
        float ex0 = __expf(fminf(fmaxf(p0 * 0.25f, -50.f), 50.f));
        float ex1 = __expf(fminf(fmaxf(p1 * 0.25f, -50.f), 50.f));
        s_acc += ex0 + ex1;
        if ((lane & 3) == 0) {
            exb[(long)e * HH + h] = ex0;
            exb[(long)(e + 1) * HH + h] = ex1;
        }
    }
    if (e < end) {
        int s0 = csr[e];
        float d0 = degn[s0];
        float4 k0 = *(const float4*)(qkv + (long)s0 * 384 + 128 + lane * 4);
        float p0 = qv.x * (k0.x + d0 * wk.x) + qv.y * (k0.y + d0 * wk.y)
                 + qv.z * (k0.z + d0 * wk.z) + qv.w * (k0.w + d0 * wk.w);
        p0 += __shfl_xor_sync(0xffffffffu, p0, 1);
        p0 += __shfl_xor_sync(0xffffffffu, p0, 2);
        float ex0 = __expf(fminf(fmaxf(p0 * 0.25f, -50.f), 50.f));
        s_acc += ex0;
        if ((lane & 3) == 0) exb[(long)e * HH + h] = ex0;
    }
    float rs = 1.0f / (s_acc + 1e-16f);

    float ax = 0.f, ay = 0.f, az = 0.f, aw = 0.f;
    e = beg;
    for (; e + 1 < end; e += 2) {
        int s0 = csr[e], s1 = csr[e + 1];
        float a0 = exb[(long)e * HH + h] * rs;
        float a1 = exb[(long)(e + 1) * HH + h] * rs;
        float d0 = degn[s0], d1 = degn[s1];
        float4 v0 = *(const float4*)(qkv + (long)s0 * 384 + 256 + lane * 4);
        float4 v1 = *(const float4*)(qkv + (long)s1 * 384 + 256 + lane * 4);
        ax += a0 * (v0.x + d0 * wv.x) + a1 * (v1.x + d1 * wv.x);
        ay += a0 * (v0.y + d0 * wv.y) + a1 * (v1.y + d1 * wv.y);
        az += a0 * (v0.z + d0 * wv.z) + a1 * (v1.z + d1 * wv.z);
        aw += a0 * (v0.w + d0 * wv.w) + a1 * (v1.w + d1 * wv.w);
    }
    if (e < end) {
        int s0 = csr[e];
        float a0 = exb[(long)e * HH + h] * rs;
        float d0 = degn[s0];
        float4 v0 = *(const float4*)(qkv + (long)s0 * 384 + 256 + lane * 4);
        ax += a0 * (v0.x + d0 * wv.x);
        ay += a0 * (v0.y + d0 * wv.y);
        az += a0 * (v0.z + d0 * wv.z);
        aw += a0 * (v0.w + d0 * wv.w);
    }
    float4 o4;
    o4.x = rnd32(ax); o4.y = rnd32(ay); o4.z = rnd32(az); o4.w = rnd32(aw);
    *(float4*)(aggr + (long)w * DD + lane * 4) = o4;
}

// ---------------- driver --------------------------------------------------------
extern "C" void kernel_launch(void* const* d_in, const int* in_sizes, int n_in,
                              void* d_out, int out_size) {
    const float* x    = (const float*)d_in[0];
    const int*   ei   = (const int*)d_in[1];
    const float* Wq   = (const float*)d_in[2];
    const float* Wk   = (const float*)d_in[3];
    const float* Wv   = (const float*)d_in[4];
    const float* Wo   = (const float*)d_in[5];
    const float* Wpos = (const float*)d_in[6];
    const float* Wdeg = (const float*)d_in[7];
    const float* W1   = (const float*)d_in[8];
    const float* W2   = (const float*)d_in[9];
    const float* bq   = (const float*)d_in[10];
    const float* bk   = (const float*)d_in[11];
    const float* bv   = (const float*)d_in[12];
    const float* bo   = (const float*)d_in[13];
    const float* bpos = (const float*)d_in[14];
    const float* bdeg = (const float*)d_in[15];
    const float* ln1b = (const float*)d_in[16];
    const float* ln2b = (const float*)d_in[17];
    const float* b1   = (const float*)d_in[18];
    const float* b2   = (const float*)d_in[19];
    const float* ln1g = (const float*)d_in[20];
    const float* ln2g = (const float*)d_in[21];
    float* xbuf = (float*)d_out;

    float *xn, *qkv, *aggr, *hb, *exb, *deg, *degn, *weff, *beff, *wde;
    float *wo, *w1, *w2;
    int *ddeg, *off, *cur, *csr;
    double* stats;
    cudaGetSymbolAddress((void**)&xn,    g_xn);
    cudaGetSymbolAddress((void**)&qkv,   g_qkv);
    cudaGetSymbolAddress((void**)&aggr,  g_aggr);
    cudaGetSymbolAddress((void**)&hb,    g_h);
    cudaGetSymbolAddress((void**)&exb,   g_ex);
    cudaGetSymbolAddress((void**)&deg,   g_deg);
    cudaGetSymbolAddress((void**)&degn,  g_degn);
    cudaGetSymbolAddress((void**)&weff,  g_weff);
    cudaGetSymbolAddress((void**)&beff,  g_beff);
    cudaGetSymbolAddress((void**)&wde,   g_wdegeff);
    cudaGetSymbolAddress((void**)&wo,    g_wo);
    cudaGetSymbolAddress((void**)&w1,    g_w1);
    cudaGetSymbolAddress((void**)&w2,    g_w2);
    cudaGetSymbolAddress((void**)&ddeg,  g_ddeg);
    cudaGetSymbolAddress((void**)&off,   g_off);
    cudaGetSymbolAddress((void**)&cur,   g_cur);
    cudaGetSymbolAddress((void**)&csr,   g_csr);
    cudaGetSymbolAddress((void**)&stats, g_stats);

    cudaFuncSetAttribute(gemm_tc, cudaFuncAttributeMaxDynamicSharedMemorySize,
                         GEMM_SMEM);

    cudaMemcpyAsync(xbuf, x, (size_t)NN * DD * sizeof(float), cudaMemcpyDeviceToDevice);

    const int rowBlocks = (NN + BM - 1) / BM;
    const int lnBlocks  = (NN + 7) / 8;
    const int nodeWarpBlocks = (NN + 7) / 8;

    // prefix kept so ncu (-s 5 -c 1) lands on the QKV GEMM
    k_weff<<<3 * DD, DD>>>(Wq, Wk, Wv, Wpos, Wdeg, bq, bk, bv, bpos, bdeg,
                           weff, beff, wde);
    k_layernorm<<<lnBlocks, 256>>>(xbuf, ln1g, ln1b, xn);
    k_prep<<<(NN + 255) / 256, 256>>>(deg, ddeg, stats);
    gemm_tc<<<dim3(3 * DD / BN, rowBlocks), 256, GEMM_SMEM>>>(
        xn, weff, qkv, beff, NN, 3 * DD, DD, 0);

    k_degcount2<<<(EE + 255) / 256, 256>>>(ei, deg, ddeg);
    k_scan<<<1, 1024>>>(ddeg, off);
    k_deg_reduce<<<148, 256>>>(deg, stats);
    k_deg_norm<<<(NN + 255) / 256, 256>>>(deg, stats, degn);
    k_csr_self<<<(NN + 255) / 256, 256>>>(off, cur, csr);
    k_csr_scatter<<<(EE + 255) / 256, 256>>>(ei, cur, csr);

    for (int l = 0; l < LL; l++) {
        k_attn<<<nodeWarpBlocks, 256>>>(off, csr, qkv, degn, wde, exb, aggr);
        k_roundw<<<(DD * FFD + 255) / 256, 256>>>(Wo + (size_t)l * DD * DD,
                                                  W1 + (size_t)l * DD * FFD,
                                                  W2 + (size_t)l * FFD * DD, wo, w1, w2);
        gemm_tc<<<dim3(DD / BN, rowBlocks), 256, GEMM_SMEM>>>(
            aggr, wo, xbuf, bo + l * DD, NN, DD, DD, 1);
        k_layernorm<<<lnBlocks, 256>>>(xbuf, ln2g + l * DD, ln2b + l * DD, xn);
        gemm_tc<<<dim3(FFD / BN, rowBlocks), 256, GEMM_SMEM>>>(
            xn, w1, hb, b1 + l * FFD, NN, FFD, DD, 2);
        gemm_tc<<<dim3(DD / BN, rowBlocks), 256, GEMM_SMEM>>>(
            hb, w2, xbuf, b2 + l * DD, NN, DD, FFD, 1);
        if (l + 1 < LL) {
            int n = l + 1;
            k_weff<<<3 * DD, DD>>>(Wq + (size_t)n * DD * DD, Wk + (size_t)n * DD * DD,
                                   Wv + (size_t)n * DD * DD, Wpos + (size_t)n * DD * DD,
                                   Wdeg + (size_t)n * DD,
                                   bq + n * DD, bk + n * DD, bv + n * DD,
                                   bpos + n * DD, bdeg + n * DD, weff, beff, wde);
            k_layernorm<<<lnBlocks, 256>>>(xbuf, ln1g + n * DD, ln1b + n * DD, xn);
            gemm_tc<<<dim3(3 * DD / BN, rowBlocks), 256, GEMM_SMEM>>>(
                xn, weff, qkv, beff, NN, 3 * DD, DD, 0);
        }
    }
}

// round 8
// speedup vs baseline: 3.1602x; 1.3911x over previous
#include <cuda_runtime.h>
#include <cuda_fp16.h>
#include <math.h>

#define NN 50000
#define EE 500000
#define DD 128
#define HH 8
#define LL 2
#define FFD 512
#define NE (EE + NN)

// ---------------- scratch ----------------------------------------------------
__device__ __align__(16) __half g_xn[NN * DD];
__device__ __align__(16) __half g_qkv[NN * 3 * DD];
__device__ __align__(16) __half g_aggr[NN * DD];
__device__ __align__(16) __half g_h[NN * FFD];
__device__ float  g_deg[NN];
__device__ float  g_degn[NN];
__device__ double g_stats[2];
__device__ __align__(16) __half g_weff[3 * DD * DD];  // transposed [384][128]
__device__ float  g_beff[3 * DD];
__device__ float  g_wdegeff[3 * DD];
__device__ __align__(16) __half g_wo[DD * DD];        // transposed [128][128]
__device__ __align__(16) __half g_w1[FFD * DD];       // transposed [512][128]
__device__ __align__(16) __half g_w2[DD * FFD];       // transposed [128][512]
__device__ int    g_ddeg[NN];
__device__ int    g_off[NN + 1];
__device__ int    g_cur[NN];
__device__ int    g_csr[NE];

__device__ __forceinline__ unsigned h2u(__half2 h) {
    unsigned u;
    memcpy(&u, &h, 4);
    return u;
}

// ---------------- prep --------------------------------------------------------
__global__ void k_prep(float* deg, int* ddeg, double* st) {
    int i = blockIdx.x * blockDim.x + threadIdx.x;
    if (i < NN) { deg[i] = 1.f; ddeg[i] = 1; }
    if (i == 0) { st[0] = 0.0; st[1] = 0.0; }
}

// ---------------- degree + CSR build -------------------------------------------
__global__ void k_degcount2(const int* __restrict__ ei, float* deg, int* ddeg) {
    int e = blockIdx.x * blockDim.x + threadIdx.x;
    if (e < EE) {
        atomicAdd(&deg[ei[e]], 1.0f);
        atomicAdd(&ddeg[ei[EE + e]], 1);
    }
}
__global__ void k_scan(const int* __restrict__ ddeg, int* __restrict__ off) {
    __shared__ int wsum[32];
    __shared__ int carry;
    int t = threadIdx.x, lane = t & 31, wid = t >> 5;
    if (t == 0) { carry = 0; off[0] = 0; }
    __syncthreads();
    for (int base = 0; base < NN; base += 1024) {
        int i = base + t;
        int v = (i < NN) ? ddeg[i] : 0;
        int s = v;
        #pragma unroll
        for (int o = 1; o < 32; o <<= 1) {
            int u = __shfl_up_sync(0xffffffffu, s, o);
            if (lane >= o) s += u;
        }
        if (lane == 31) wsum[wid] = s;
        __syncthreads();
        if (wid == 0) {
            int ws = wsum[lane];
            #pragma unroll
            for (int o = 1; o < 32; o <<= 1) {
                int u = __shfl_up_sync(0xffffffffu, ws, o);
                if (lane >= o) ws += u;
            }
            wsum[lane] = ws;
        }
        __syncthreads();
        int add = (wid > 0) ? wsum[wid - 1] : 0;
        int incl = s + add + carry;
        if (i < NN) off[i + 1] = incl;
        __syncthreads();
        if (t == 1023) carry = incl;
        __syncthreads();
    }
}
__global__ void k_csr_self(const int* __restrict__ off, int* cur, int* csr) {
    int i = blockIdx.x * blockDim.x + threadIdx.x;
    if (i >= NN) return;
    int o = off[i];
    csr[o] = i;
    cur[i] = o + 1;
}
__global__ void k_csr_scatter(const int* __restrict__ ei, int* cur, int* csr) {
    int e = blockIdx.x * blockDim.x + threadIdx.x;
    if (e >= EE) return;
    int dst = ei[EE + e];
    int pos = atomicAdd(&cur[dst], 1);
    csr[pos] = ei[e];
}

__global__ void k_deg_reduce(const float* __restrict__ deg, double* st) {
    __shared__ double ss[256], sq[256];
    int t = threadIdx.x;
    double s = 0.0, q = 0.0;
    for (int i = blockIdx.x * blockDim.x + t; i < NN; i += gridDim.x * blockDim.x) {
        double d = (double)deg[i];
        s += d; q += d * d;
    }
    ss[t] = s; sq[t] = q;
    __syncthreads();
    for (int o = 128; o > 0; o >>= 1) {
        if (t < o) { ss[t] += ss[t + o]; sq[t] += sq[t + o]; }
        __syncthreads();
    }
    if (t == 0) { atomicAdd(&st[0], ss[0]); atomicAdd(&st[1], sq[0]); }
}
__global__ void k_deg_norm(const float* __restrict__ deg, const double* __restrict__ st,
                           float* __restrict__ degn) {
    int i = blockIdx.x * blockDim.x + threadIdx.x;
    if (i >= NN) return;
    double mean = st[0] / (double)NN;
    double var  = (st[1] - st[0] * st[0] / (double)NN) / (double)(NN - 1);
    float  sd   = (float)sqrt(var);
    degn[i] = (deg[i] - (float)mean) / (sd + 1e-6f);
}

// ---------------- folded effective weights (fp16, TRANSPOSED [N][K]) -----------
__global__ void k_weff(const float* __restrict__ Wq, const float* __restrict__ Wk,
                       const float* __restrict__ Wv, const float* __restrict__ Wpos,
                       const float* __restrict__ Wdeg,
                       const float* __restrict__ bq, const float* __restrict__ bk,
                       const float* __restrict__ bv, const float* __restrict__ bpos,
                       const float* __restrict__ bdeg,
                       __half* __restrict__ weff, float* __restrict__ beff,
                       float* __restrict__ wdegeff) {
    int j = blockIdx.x;
    int t = threadIdx.x;
    const float* W  = (j < DD) ? Wq : ((j < 2 * DD) ? Wk : Wv);
    const float* bb = (j < DD) ? bq : ((j < 2 * DD) ? bk : bv);
    int jj = j & (DD - 1);
    __shared__ float col[DD];
    col[t] = W[t * DD + jj];
    __syncthreads();
    float acc = col[t];
    #pragma unroll 8
    for (int m = 0; m < DD; m++) acc += Wpos[t * DD + m] * col[m];
    weff[j * DD + t] = __float2half_rn(acc);
    if (t == 0) {
        float s = 0.f;
        for (int m = 0; m < DD; m++) s += (bpos[m] + bdeg[m]) * col[m];
        beff[j] = s + bb[jj];
    }
    if (t == 1) {
        float s = 0.f;
        for (int m = 0; m < DD; m++) s += Wdeg[m] * col[m];
        wdegeff[j] = s;
    }
}

// convert + transpose weights to fp16 [N][K]
__global__ void k_cvtw(const float* __restrict__ Wo, const float* __restrict__ W1,
                       const float* __restrict__ W2, __half* wo, __half* w1, __half* w2) {
    int i = blockIdx.x * blockDim.x + threadIdx.x;
    if (i < DD * DD) {
        int k = i / DD, n = i % DD;
        wo[n * DD + k] = __float2half_rn(Wo[i]);
    }
    if (i < DD * FFD) {
        int k1 = i / FFD, n1 = i % FFD;
        w1[n1 * DD + k1] = __float2half_rn(W1[i]);
        int k2 = i / DD, n2 = i % DD;
        w2[n2 * FFD + k2] = __float2half_rn(W2[i]);
    }
}

// ---------------- LayerNorm (warp per node, fp16 output) -----------------------
__global__ void k_layernorm(const float* __restrict__ x, const float* __restrict__ g,
                            const float* __restrict__ b, __half* __restrict__ out) {
    int node = (blockIdx.x * blockDim.x + threadIdx.x) >> 5;
    int lane = threadIdx.x & 31;
    if (node >= NN) return;
    const float4 v = *(const float4*)(x + (long)node * DD + lane * 4);
    float s = v.x + v.y + v.z + v.w;
    #pragma unroll
    for (int o = 16; o > 0; o >>= 1) s += __shfl_xor_sync(0xffffffffu, s, o);
    float mu = s * (1.0f / DD);
    float dx = v.x - mu, dy = v.y - mu, dz = v.z - mu, dw = v.w - mu;
    float q = dx * dx + dy * dy + dz * dz + dw * dw;
    #pragma unroll
    for (int o = 16; o > 0; o >>= 1) q += __shfl_xor_sync(0xffffffffu, q, o);
    float rs = rsqrtf(q * (1.0f / DD) + 1e-5f);
    const float4 gg = *(const float4*)(g + lane * 4);
    const float4 bb = *(const float4*)(b + lane * 4);
    __half2 h0 = __floats2half2_rn(dx * rs * gg.x + bb.x, dy * rs * gg.y + bb.y);
    __half2 h1 = __floats2half2_rn(dz * rs * gg.z + bb.z, dw * rs * gg.w + bb.w);
    uint2 u = make_uint2(h2u(h0), h2u(h1));
    *(uint2*)(out + (long)node * DD + lane * 4) = u;
}

// ---------------- 3-stage pipelined fp16 GEMM (m16n8k16, fp32 accum) -----------
// C[M,N] = A[M,K] @ Bt[N,K]^T (+epilogue). A,Bt fp16.
// mode 0: half out = acc + bias
// mode 1: float out = acc + bias + C
// mode 2: half out = gelu(acc + bias)
#define BM 128
#define BN 128
#define BKH 32                  // K halves per block
#define LDH 40                  // halves per smem row (80B, conflict-free)
#define NSTAGE 3
#define STAGE_H (BM * LDH)      // halves per stage (per operand)

__device__ __forceinline__ unsigned smemu32(const void* p) {
    return (unsigned)__cvta_generic_to_shared(p);
}

__global__ __launch_bounds__(256, 2) void gemm_hf(
    const __half* __restrict__ A, const __half* __restrict__ Bt, void* Cv,
    const float* __restrict__ bias, int M, int N, int K, int mode) {
    extern __shared__ __half sm[];
    __half* As = sm;                           // [NSTAGE][BM][LDH]
    __half* Bs = sm + NSTAGE * STAGE_H;        // [NSTAGE][BN][LDH]

    const int tid  = threadIdx.x;
    const int warp = tid >> 5;
    const int lane = tid & 31;
    const int wm = warp >> 1;
    const int wn = warp & 1;
    const int g  = lane >> 2;
    const int q  = lane & 3;
    const int rowBase = blockIdx.y * BM;
    const int colBase = blockIdx.x * BN;

    float acc[2][8][4];
    #pragma unroll
    for (int i = 0; i < 2; i++)
        #pragma unroll
        for (int j = 0; j < 8; j++)
            #pragma unroll
            for (int k = 0; k < 4; k++) acc[i][j][k] = 0.0f;

    const int nk = K / BKH;

    auto loadA = [&](int s, int k0) {
        #pragma unroll
        for (int i = 0; i < 2; i++) {
            int idx = tid + i * 256;
            int r = idx >> 2, c = (idx & 3) * 8;
            int grow = rowBase + r;
            const __half* src = A + (long)(grow < M ? grow : M - 1) * K + k0 + c;
            int sz = (grow < M) ? 16 : 0;
            asm volatile("cp.async.cg.shared.global [%0], [%1], 16, %2;"
                         :: "r"(smemu32(As + s * STAGE_H + r * LDH + c)), "l"(src), "r"(sz));
        }
    };
    auto loadB = [&](int s, int k0) {
        #pragma unroll
        for (int i = 0; i < 2; i++) {
            int idx = tid + i * 256;
            int n = idx >> 2, c = (idx & 3) * 8;
            const __half* src = Bt + (long)(colBase + n) * K + k0 + c;
            asm volatile("cp.async.cg.shared.global [%0], [%1], 16;"
                         :: "r"(smemu32(Bs + s * STAGE_H + n * LDH + c)), "l"(src));
        }
    };

    // ldmatrix per-thread byte offsets within a stage
    unsigned aBase = smemu32(As);
    unsigned bBase = smemu32(Bs);
    unsigned offA[2], offB[4];
    #pragma unroll
    for (int mt = 0; mt < 2; mt++) {
        int row = wm * 32 + mt * 16 + (lane & 15);
        int kh  = (lane >> 4) << 3;               // 0 or 8 halves
        offA[mt] = (unsigned)((row * LDH + kh) * 2);
    }
    #pragma unroll
    for (int p = 0; p < 4; p++) {
        int row = wn * 64 + p * 16 + ((lane >> 4) << 3) + (lane & 7);
        int kh  = ((lane >> 3) & 1) << 3;
        offB[p] = (unsigned)((row * LDH + kh) * 2);
    }
    const unsigned stageBytes = STAGE_H * 2;

    loadA(0, 0); loadB(0, 0);
    asm volatile("cp.async.commit_group;");
    if (nk > 1) { loadA(1, BKH); loadB(1, BKH); }
    asm volatile("cp.async.commit_group;");

    int buf = 0;
    for (int kb = 0; kb < nk; kb++) {
        asm volatile("cp.async.wait_group 1;");
        __syncthreads();
        if (kb + 2 < nk) {
            int s = (kb + 2) % NSTAGE;
            loadA(s, (kb + 2) * BKH);
            loadB(s, (kb + 2) * BKH);
        }
        asm volatile("cp.async.commit_group;");

        unsigned aStage = aBase + buf * stageBytes;
        unsigned bStage = bBase + buf * stageBytes;
        #pragma unroll
        for (int kk = 0; kk < BKH; kk += 16) {     // two k16 steps
            unsigned a_frag[2][4];
            #pragma unroll
            for (int mt = 0; mt < 2; mt++) {
                asm volatile("ldmatrix.sync.aligned.m8n8.x4.shared.b16 "
                             "{%0,%1,%2,%3}, [%4];"
                             : "=r"(a_frag[mt][0]), "=r"(a_frag[mt][1]),
                               "=r"(a_frag[mt][2]), "=r"(a_frag[mt][3])
                             : "r"(aStage + offA[mt] + kk * 2));
            }
            unsigned b_frag[8][2];
            #pragma unroll
            for (int p = 0; p < 4; p++) {
                asm volatile("ldmatrix.sync.aligned.m8n8.x4.shared.b16 "
                             "{%0,%1,%2,%3}, [%4];"
                             : "=r"(b_frag[2 * p][0]), "=r"(b_frag[2 * p][1]),
                               "=r"(b_frag[2 * p + 1][0]), "=r"(b_frag[2 * p + 1][1])
                             : "r"(bStage + offB[p] + kk * 2));
            }
            #pragma unroll
            for (int mt = 0; mt < 2; mt++)
                #pragma unroll
                for (int nt = 0; nt < 8; nt++) {
                    asm volatile(
                        "mma.sync.aligned.m16n8k16.row.col.f32.f16.f16.f32 "
                        "{%0,%1,%2,%3}, {%4,%5,%6,%7}, {%8,%9}, {%0,%1,%2,%3};"
                        : "+f"(acc[mt][nt][0]), "+f"(acc[mt][nt][1]),
                          "+f"(acc[mt][nt][2]), "+f"(acc[mt][nt][3])
                        : "r"(a_frag[mt][0]), "r"(a_frag[mt][1]),
                          "r"(a_frag[mt][2]), "r"(a_frag[mt][3]),
                          "r"(b_frag[nt][0]), "r"(b_frag[nt][1]));
                }
        }
        __syncthreads();
        buf = (buf + 1 == NSTAGE) ? 0 : buf + 1;
    }

    #pragma unroll
    for (int mt = 0; mt < 2; mt++) {
        #pragma unroll
        for (int half = 0; half < 2; half++) {
            int gr = rowBase + wm * 32 + mt * 16 + g + half * 8;
            if (gr >= M) continue;
            #pragma unroll
            for (int nt = 0; nt < 8; nt++) {
                int gc = colBase + wn * 64 + nt * 8 + q * 2;
                float v0 = acc[mt][nt][half * 2 + 0] + bias[gc];
                float v1 = acc[mt][nt][half * 2 + 1] + bias[gc + 1];
                if (mode == 1) {
                    float* cp = (float*)Cv + (long)gr * N + gc;
                    float2 old = *(const float2*)cp;
                    *(float2*)cp = make_float2(v0 + old.x, v1 + old.y);
                } else {
                    if (mode == 2) {
                        v0 = 0.5f * v0 * (1.0f + erff(v0 * 0.70710678118654752f));
                        v1 = 0.5f * v1 * (1.0f + erff(v1 * 0.70710678118654752f));
                    }
                    __half* cp = (__half*)Cv + (long)gr * N + gc;
                    *(__half2*)cp = __floats2half2_rn(v0, v1);
                }
            }
        }
    }
}
#define GEMM_SMEM (NSTAGE * STAGE_H * 2 * (int)sizeof(__half))

// ---------------- fused single-pass CSR attention (warp per dst node) ----------
__device__ __forceinline__ float4 ld4h(const __half* p) {
    uint2 u = *(const uint2*)p;
    __half2 h0, h1;
    memcpy(&h0, &u.x, 4);
    memcpy(&h1, &u.y, 4);
    float2 a = __half22float2(h0);
    float2 b = __half22float2(h1);
    return make_float4(a.x, a.y, b.x, b.y);
}

__global__ __launch_bounds__(256) void k_attn(
    const int* __restrict__ off, const int* __restrict__ csr,
    const __half* __restrict__ qkv, const float* __restrict__ degn,
    const float* __restrict__ wde, __half* __restrict__ aggr) {
    int w = (blockIdx.x * blockDim.x + threadIdx.x) >> 5;
    int lane = threadIdx.x & 31;
    if (w >= NN) return;
    const int beg = off[w], end = off[w + 1];

    const float4 wq = *(const float4*)(wde + lane * 4);
    const float4 wk = *(const float4*)(wde + 128 + lane * 4);
    const float4 wv = *(const float4*)(wde + 256 + lane * 4);

    float dnd = degn[w];
    float4 qv = ld4h(qkv + (long)w * 384 + lane * 4);
    qv.x += dnd * wq.x; qv.y += dnd * wq.y; qv.z += dnd * wq.z; qv.w += dnd * wq.w;

    float s_acc = 0.0f;
    float ax = 0.f, ay = 0.f, az = 0.f, aw = 0.f;
    int e = beg;
    for (; e + 1 < end; e += 2) {
        int s0 = csr[e], s1 = csr[e + 1];
        float d0 = degn[s0], d1 = degn[s1];
        float4 k0 = ld4h(qkv + (long)s0 * 384 + 128 + lane * 4);
        float4 k1 = ld4h(qkv + (long)s1 * 384 + 128 + lane * 4);
        float4 v0 = ld4h(qkv + (long)s0 * 384 + 256 + lane * 4);
        float4 v1 = ld4h(qkv + (long)s1 * 384 + 256 + lane * 4);
        float p0 = qv.x * (k0.x + d0 * wk.x) + qv.y * (k0.y + d0 * wk.y)
                 + qv.z * (k0.z + d0 * wk.z) + qv.w * (k0.w + d0 * wk.w);
        float p1 = qv.x * (k1.x + d1 * wk.x) + qv.y * (k1.y + d1 * wk.y)
                 + qv.z * (k1.z + d1 * wk.z) + qv.w * (k1.w + d1 * wk.w);
        p0 += __shfl_xor_sync(0xffffffffu, p0, 1);
        p0 += __shfl_xor_sync(0xffffffffu, p0, 2);
        p1 += __shfl_xor_sync(0xffffffffu, p1, 1);
        p1 += __shfl_xor_sync(0xffffffffu, p1, 2);
        float ex0 = __expf(fminf(fmaxf(p0 * 0.25f, -50.f), 50.f));
        float ex1 = __expf(fminf(fmaxf(p1 * 0.25f, -50.f), 50.f));
        s_acc += ex0 + ex1;
        ax += ex0 * (v0.x + d0 * wv.x) + ex1 * (v1.x + d1 * wv.x);
        ay += ex0 * (v0.y + d0 * wv.y) + ex1 * (v1.y + d1 * wv.y);
        az += ex0 * (v0.z + d0 * wv.z) + ex1 * (v1.z + d1 * wv.z);
        aw += ex0 * (v0.w + d0 * wv.w) + ex1 * (v1.w + d1 * wv.w);
    }
    if (e < end) {
        int s0 = csr[e];
        float d0 = degn[s0];
        float4 k0 = ld4h(qkv + (long)s0 * 384 + 128 + lane * 4);
        float4 v0 = ld4h(qkv + (long)s0 * 384 + 256 + lane * 4);
        float p0 = qv.x * (k0.x + d0 * wk.x) + qv.y * (k0.y + d0 * wk.y)
                 + qv.z * (k0.z + d0 * wk.z) + qv.w * (k0.w + d0 * wk.w);
        p0 += __shfl_xor_sync(0xffffffffu, p0, 1);
        p0 += __shfl_xor_sync(0xffffffffu, p0, 2);
        float ex0 = __expf(fminf(fmaxf(p0 * 0.25f, -50.f), 50.f));
        s_acc += ex0;
        ax += ex0 * (v0.x + d0 * wv.x);
        ay += ex0 * (v0.y + d0 * wv.y);
        az += ex0 * (v0.z + d0 * wv.z);
        aw += ex0 * (v0.w + d0 * wv.w);
    }
    float rs = 1.0f / (s_acc + 1e-16f);
    __half2 h0 = __floats2half2_rn(ax * rs, ay * rs);
    __half2 h1 = __floats2half2_rn(az * rs, aw * rs);
    uint2 u = make_uint2(h2u(h0), h2u(h1));
    *(uint2*)(aggr + (long)w * DD + lane * 4) = u;
}

// ---------------- driver --------------------------------------------------------
extern "C" void kernel_launch(void* const* d_in, const int* in_sizes, int n_in,
                              void* d_out, int out_size) {
    const float* x    = (const float*)d_in[0];
    const int*   ei   = (const int*)d_in[1];
    const float* Wq   = (const float*)d_in[2];
    const float* Wk   = (const float*)d_in[3];
    const float* Wv   = (const float*)d_in[4];
    const float* Wo   = (const float*)d_in[5];
    const float* Wpos = (const float*)d_in[6];
    const float* Wdeg = (const float*)d_in[7];
    const float* W1   = (const float*)d_in[8];
    const float* W2   = (const float*)d_in[9];
    const float* bq   = (const float*)d_in[10];
    const float* bk   = (const float*)d_in[11];
    const float* bv   = (const float*)d_in[12];
    const float* bo   = (const float*)d_in[13];
    const float* bpos = (const float*)d_in[14];
    const float* bdeg = (const float*)d_in[15];
    const float* ln1b = (const float*)d_in[16];
    const float* ln2b = (const float*)d_in[17];
    const float* b1   = (const float*)d_in[18];
    const float* b2   = (const float*)d_in[19];
    const float* ln1g = (const float*)d_in[20];
    const float* ln2g = (const float*)d_in[21];
    float* xbuf = (float*)d_out;

    __half *xn, *qkv, *aggr, *hb, *weff, *wo, *w1, *w2;
    float *deg, *degn, *beff, *wde;
    int *ddeg, *off, *cur, *csr;
    double* stats;
    cudaGetSymbolAddress((void**)&xn,    g_xn);
    cudaGetSymbolAddress((void**)&qkv,   g_qkv);
    cudaGetSymbolAddress((void**)&aggr,  g_aggr);
    cudaGetSymbolAddress((void**)&hb,    g_h);
    cudaGetSymbolAddress((void**)&deg,   g_deg);
    cudaGetSymbolAddress((void**)&degn,  g_degn);
    cudaGetSymbolAddress((void**)&weff,  g_weff);
    cudaGetSymbolAddress((void**)&beff,  g_beff);
    cudaGetSymbolAddress((void**)&wde,   g_wdegeff);
    cudaGetSymbolAddress((void**)&wo,    g_wo);
    cudaGetSymbolAddress((void**)&w1,    g_w1);
    cudaGetSymbolAddress((void**)&w2,    g_w2);
    cudaGetSymbolAddress((void**)&ddeg,  g_ddeg);
    cudaGetSymbolAddress((void**)&off,   g_off);
    cudaGetSymbolAddress((void**)&cur,   g_cur);
    cudaGetSymbolAddress((void**)&csr,   g_csr);
    cudaGetSymbolAddress((void**)&stats, g_stats);

    cudaFuncSetAttribute(gemm_hf, cudaFuncAttributeMaxDynamicSharedMemorySize,
                         GEMM_SMEM);

    cudaMemcpyAsync(xbuf, x, (size_t)NN * DD * sizeof(float), cudaMemcpyDeviceToDevice);

    const int rowBlocks = (NN + BM - 1) / BM;
    const int lnBlocks  = (NN + 7) / 8;
    const int nodeWarpBlocks = (NN + 7) / 8;

    // prefix kept so ncu (-s 5 -c 1) lands on the QKV GEMM
    k_weff<<<3 * DD, DD>>>(Wq, Wk, Wv, Wpos, Wdeg, bq, bk, bv, bpos, bdeg,
                           weff, beff, wde);
    k_layernorm<<<lnBlocks, 256>>>(xbuf, ln1g, ln1b, xn);
    k_prep<<<(NN + 255) / 256, 256>>>(deg, ddeg, stats);
    gemm_hf<<<dim3(3 * DD / BN, rowBlocks), 256, GEMM_SMEM>>>(
        xn, weff, qkv, beff, NN, 3 * DD, DD, 0);

    k_degcount2<<<(EE + 255) / 256, 256>>>(ei, deg, ddeg);
    k_scan<<<1, 1024>>>(ddeg, off);
    k_deg_reduce<<<148, 256>>>(deg, stats);
    k_deg_norm<<<(NN + 255) / 256, 256>>>(deg, stats, degn);
    k_csr_self<<<(NN + 255) / 256, 256>>>(off, cur, csr);
    k_csr_scatter<<<(EE + 255) / 256, 256>>>(ei, cur, csr);

    for (int l = 0; l < LL; l++) {
        k_attn<<<nodeWarpBlocks, 256>>>(off, csr, qkv, degn, wde, aggr);
        k_cvtw<<<(DD * FFD + 255) / 256, 256>>>(Wo + (size_t)l * DD * DD,
                                                W1 + (size_t)l * DD * FFD,
                                                W2 + (size_t)l * FFD * DD, wo, w1, w2);
        gemm_hf<<<dim3(DD / BN, rowBlocks), 256, GEMM_SMEM>>>(
            aggr, wo, xbuf, bo + l * DD, NN, DD, DD, 1);
        k_layernorm<<<lnBlocks, 256>>>(xbuf, ln2g + l * DD, ln2b + l * DD, xn);
        gemm_hf<<<dim3(FFD / BN, rowBlocks), 256, GEMM_SMEM>>>(
            xn, w1, hb, b1 + l * FFD, NN, FFD, DD, 2);
        gemm_hf<<<dim3(DD / BN, rowBlocks), 256, GEMM_SMEM>>>(
            hb, w2, xbuf, b2 + l * DD, NN, DD, FFD, 1);
        if (l + 1 < LL) {
            int n = l + 1;
            k_weff<<<3 * DD, DD>>>(Wq + (size_t)n * DD * DD, Wk + (size_t)n * DD * DD,
                                   Wv + (size_t)n * DD * DD, Wpos + (size_t)n * DD * DD,
                                   Wdeg + (size_t)n * DD,
                                   bq + n * DD, bk + n * DD, bv + n * DD,
                                   bpos + n * DD, bdeg + n * DD, weff, beff, wde);
            k_layernorm<<<lnBlocks, 256>>>(xbuf, ln1g + n * DD, ln1b + n * DD, xn);
            gemm_hf<<<dim3(3 * DD / BN, rowBlocks), 256, GEMM_SMEM>>>(
                xn, weff, qkv, beff, NN, 3 * DD, DD, 0);
        }
    }
}

// round 9
// speedup vs baseline: 3.2366x; 1.0242x over previous
#include <cuda_runtime.h>
#include <cuda_fp16.h>
#include <math.h>

#define NN 50000
#define EE 500000
#define DD 128
#define HH 8
#define LL 2
#define FFD 512
#define NE (EE + NN)

// ---------------- scratch ----------------------------------------------------
__device__ __align__(16) __half g_xn[NN * DD];
__device__ __align__(16) __half g_qkv[NN * 3 * DD];
__device__ __align__(16) __half g_aggr[NN * DD];
__device__ __align__(16) __half g_h[NN * FFD];
__device__ float  g_deg[NN];
__device__ float  g_degn[NN];
__device__ double g_stats[2];
__device__ __align__(16) __half g_weff[3 * DD * DD];  // transposed [384][128]
__device__ float  g_beff[3 * DD];
__device__ float  g_wdegeff[3 * DD];
__device__ __align__(16) __half g_wo[DD * DD];        // transposed [128][128]
__device__ __align__(16) __half g_w1[FFD * DD];       // transposed [512][128]
__device__ __align__(16) __half g_w2[DD * FFD];       // transposed [128][512]
__device__ int    g_ddeg[NN];
__device__ int    g_off[NN + 1];
__device__ int    g_cur[NN];
__device__ int    g_csr[NE];

__device__ __forceinline__ unsigned h2u(__half2 h) {
    unsigned u;
    memcpy(&u, &h, 4);
    return u;
}

// ---------------- prep --------------------------------------------------------
__global__ void k_prep(float* deg, int* ddeg, double* st) {
    int i = blockIdx.x * blockDim.x + threadIdx.x;
    if (i < NN) { deg[i] = 1.f; ddeg[i] = 1; }
    if (i == 0) { st[0] = 0.0; st[1] = 0.0; }
}

// ---------------- degree + CSR build -------------------------------------------
__global__ void k_degcount2(const int* __restrict__ ei, float* deg, int* ddeg) {
    int e = blockIdx.x * blockDim.x + threadIdx.x;
    if (e < EE) {
        atomicAdd(&deg[ei[e]], 1.0f);
        atomicAdd(&ddeg[ei[EE + e]], 1);
    }
}
__global__ void k_scan(const int* __restrict__ ddeg, int* __restrict__ off) {
    __shared__ int wsum[32];
    __shared__ int carry;
    int t = threadIdx.x, lane = t & 31, wid = t >> 5;
    if (t == 0) { carry = 0; off[0] = 0; }
    __syncthreads();
    for (int base = 0; base < NN; base += 1024) {
        int i = base + t;
        int v = (i < NN) ? ddeg[i] : 0;
        int s = v;
        #pragma unroll
        for (int o = 1; o < 32; o <<= 1) {
            int u = __shfl_up_sync(0xffffffffu, s, o);
            if (lane >= o) s += u;
        }
        if (lane == 31) wsum[wid] = s;
        __syncthreads();
        if (wid == 0) {
            int ws = wsum[lane];
            #pragma unroll
            for (int o = 1; o < 32; o <<= 1) {
                int u = __shfl_up_sync(0xffffffffu, ws, o);
                if (lane >= o) ws += u;
            }
            wsum[lane] = ws;
        }
        __syncthreads();
        int add = (wid > 0) ? wsum[wid - 1] : 0;
        int incl = s + add + carry;
        if (i < NN) off[i + 1] = incl;
        __syncthreads();
        if (t == 1023) carry = incl;
        __syncthreads();
    }
}
__global__ void k_csr_self(const int* __restrict__ off, int* cur, int* csr) {
    int i = blockIdx.x * blockDim.x + threadIdx.x;
    if (i >= NN) return;
    int o = off[i];
    csr[o] = i;
    cur[i] = o + 1;
}
__global__ void k_csr_scatter(const int* __restrict__ ei, int* cur, int* csr) {
    int e = blockIdx.x * blockDim.x + threadIdx.x;
    if (e >= EE) return;
    int dst = ei[EE + e];
    int pos = atomicAdd(&cur[dst], 1);
    csr[pos] = ei[e];
}

__global__ void k_deg_reduce(const float* __restrict__ deg, double* st) {
    __shared__ double ss[256], sq[256];
    int t = threadIdx.x;
    double s = 0.0, q = 0.0;
    for (int i = blockIdx.x * blockDim.x + t; i < NN; i += gridDim.x * blockDim.x) {
        double d = (double)deg[i];
        s += d; q += d * d;
    }
    ss[t] = s; sq[t] = q;
    __syncthreads();
    for (int o = 128; o > 0; o >>= 1) {
        if (t < o) { ss[t] += ss[t + o]; sq[t] += sq[t + o]; }
        __syncthreads();
    }
    if (t == 0) { atomicAdd(&st[0], ss[0]); atomicAdd(&st[1], sq[0]); }
}
__global__ void k_deg_norm(const float* __restrict__ deg, const double* __restrict__ st,
                           float* __restrict__ degn) {
    int i = blockIdx.x * blockDim.x + threadIdx.x;
    if (i >= NN) return;
    double mean = st[0] / (double)NN;
    double var  = (st[1] - st[0] * st[0] / (double)NN) / (double)(NN - 1);
    float  sd   = (float)sqrt(var);
    degn[i] = (deg[i] - (float)mean) / (sd + 1e-6f);
}

// ---------------- folded effective weights (fp16, TRANSPOSED [N][K]) -----------
__global__ void k_weff(const float* __restrict__ Wq, const float* __restrict__ Wk,
                       const float* __restrict__ Wv, const float* __restrict__ Wpos,
                       const float* __restrict__ Wdeg,
                       const float* __restrict__ bq, const float* __restrict__ bk,
                       const float* __restrict__ bv, const float* __restrict__ bpos,
                       const float* __restrict__ bdeg,
                       __half* __restrict__ weff, float* __restrict__ beff,
                       float* __restrict__ wdegeff) {
    int j = blockIdx.x;
    int t = threadIdx.x;
    const float* W  = (j < DD) ? Wq : ((j < 2 * DD) ? Wk : Wv);
    const float* bb = (j < DD) ? bq : ((j < 2 * DD) ? bk : bv);
    int jj = j & (DD - 1);
    __shared__ float col[DD];
    col[t] = W[t * DD + jj];
    __syncthreads();
    float acc = col[t];
    #pragma unroll 8
    for (int m = 0; m < DD; m++) acc += Wpos[t * DD + m] * col[m];
    weff[j * DD + t] = __float2half_rn(acc);
    if (t == 0) {
        float s = 0.f;
        for (int m = 0; m < DD; m++) s += (bpos[m] + bdeg[m]) * col[m];
        beff[j] = s + bb[jj];
    }
    if (t == 1) {
        float s = 0.f;
        for (int m = 0; m < DD; m++) s += Wdeg[m] * col[m];
        wdegeff[j] = s;
    }
}

// convert + transpose weights to fp16 [N][K]
__global__ void k_cvtw(const float* __restrict__ Wo, const float* __restrict__ W1,
                       const float* __restrict__ W2, __half* wo, __half* w1, __half* w2) {
    int i = blockIdx.x * blockDim.x + threadIdx.x;
    if (i < DD * DD) {
        int k = i / DD, n = i % DD;
        wo[n * DD + k] = __float2half_rn(Wo[i]);
    }
    if (i < DD * FFD) {
        int k1 = i / FFD, n1 = i % FFD;
        w1[n1 * DD + k1] = __float2half_rn(W1[i]);
        int k2 = i / DD, n2 = i % DD;
        w2[n2 * FFD + k2] = __float2half_rn(W2[i]);
    }
}

// ---------------- LayerNorm (warp per node, fp16 output) -----------------------
__global__ void k_layernorm(const float* __restrict__ x, const float* __restrict__ g,
                            const float* __restrict__ b, __half* __restrict__ out) {
    int node = (blockIdx.x * blockDim.x + threadIdx.x) >> 5;
    int lane = threadIdx.x & 31;
    if (node >= NN) return;
    const float4 v = *(const float4*)(x + (long)node * DD + lane * 4);
    float s = v.x + v.y + v.z + v.w;
    #pragma unroll
    for (int o = 16; o > 0; o >>= 1) s += __shfl_xor_sync(0xffffffffu, s, o);
    float mu = s * (1.0f / DD);
    float dx = v.x - mu, dy = v.y - mu, dz = v.z - mu, dw = v.w - mu;
    float q = dx * dx + dy * dy + dz * dz + dw * dw;
    #pragma unroll
    for (int o = 16; o > 0; o >>= 1) q += __shfl_xor_sync(0xffffffffu, q, o);
    float rs = rsqrtf(q * (1.0f / DD) + 1e-5f);
    const float4 gg = *(const float4*)(g + lane * 4);
    const float4 bb = *(const float4*)(b + lane * 4);
    __half2 h0 = __floats2half2_rn(dx * rs * gg.x + bb.x, dy * rs * gg.y + bb.y);
    __half2 h1 = __floats2half2_rn(dz * rs * gg.z + bb.z, dw * rs * gg.w + bb.w);
    uint2 u = make_uint2(h2u(h0), h2u(h1));
    *(uint2*)(out + (long)node * DD + lane * 4) = u;
}

// ---------------- 3-stage pipelined fp16 GEMM (m16n8k16, fp32 accum) -----------
// C[M,N] = A[M,K] @ Bt[N,K]^T (+epilogue). A,Bt fp16. BN = NT*16.
// mode 0: half out  = acc + bias + degn[i]*wdeg[j]
// mode 1: float out = acc + bias + C
// mode 2: half out  = gelu(acc + bias)
#define BM 128
#define BKH 64                  // K halves per block
#define LDH 72                  // halves per smem row (144B, conflict-free)
#define NSTAGE 3
#define ASTAGE_H (BM * LDH)

__device__ __forceinline__ unsigned smemu32(const void* p) {
    return (unsigned)__cvta_generic_to_shared(p);
}

template<int NT>
__global__ __launch_bounds__(256, 2) void gemm_hf(
    const __half* __restrict__ A, const __half* __restrict__ Bt, void* Cv,
    const float* __restrict__ bias, const float* __restrict__ wdegv,
    const float* __restrict__ degn, int M, int N, int K, int mode) {
    constexpr int BN = NT * 16;
    constexpr int BSTAGE_H = BN * LDH;
    extern __shared__ __half sm[];
    __half* As = sm;                           // [NSTAGE][BM][LDH]
    __half* Bs = sm + NSTAGE * ASTAGE_H;       // [NSTAGE][BN][LDH]

    const int tid  = threadIdx.x;
    const int warp = tid >> 5;
    const int lane = tid & 31;
    const int wm = warp >> 1;
    const int wn = warp & 1;
    const int g  = lane >> 2;
    const int q  = lane & 3;
    const int rowBase = blockIdx.y * BM;
    const int colBase = blockIdx.x * BN;

    float acc[2][NT][4];
    #pragma unroll
    for (int i = 0; i < 2; i++)
        #pragma unroll
        for (int j = 0; j < NT; j++)
            #pragma unroll
            for (int k = 0; k < 4; k++) acc[i][j][k] = 0.0f;

    const int nk = K / BKH;

    auto loadA = [&](int s, int k0) {
        #pragma unroll
        for (int i = 0; i < 4; i++) {
            int idx = tid + i * 256;           // 1024 16B-chunks
            int r = idx >> 3, c = (idx & 7) * 8;
            int grow = rowBase + r;
            const __half* src = A + (long)(grow < M ? grow : M - 1) * K + k0 + c;
            int sz = (grow < M) ? 16 : 0;
            asm volatile("cp.async.cg.shared.global [%0], [%1], 16, %2;"
                         :: "r"(smemu32(As + s * ASTAGE_H + r * LDH + c)), "l"(src), "r"(sz));
        }
    };
    auto loadB = [&](int s, int k0) {
        #pragma unroll
        for (int i = 0; i < NT / 2; i++) {
            int idx = tid + i * 256;           // BN*8 chunks
            int n = idx >> 3, c = (idx & 7) * 8;
            const __half* src = Bt + (long)(colBase + n) * K + k0 + c;
            asm volatile("cp.async.cg.shared.global [%0], [%1], 16;"
                         :: "r"(smemu32(Bs + s * BSTAGE_H + n * LDH + c)), "l"(src));
        }
    };

    unsigned aBase = smemu32(As);
    unsigned bBase = smemu32(Bs);
    unsigned offA[2], offB[NT / 2];
    #pragma unroll
    for (int mt = 0; mt < 2; mt++) {
        int row = wm * 32 + mt * 16 + (lane & 15);
        int kh  = (lane >> 4) << 3;
        offA[mt] = (unsigned)((row * LDH + kh) * 2);
    }
    #pragma unroll
    for (int p = 0; p < NT / 2; p++) {
        int row = wn * (NT * 8) + p * 16 + ((lane >> 4) << 3) + (lane & 7);
        int kh  = ((lane >> 3) & 1) << 3;
        offB[p] = (unsigned)((row * LDH + kh) * 2);
    }

    loadA(0, 0); loadB(0, 0);
    asm volatile("cp.async.commit_group;");
    if (nk > 1) { loadA(1, BKH); loadB(1, BKH); }
    asm volatile("cp.async.commit_group;");

    int buf = 0;
    for (int kb = 0; kb < nk; kb++) {
        asm volatile("cp.async.wait_group 1;");
        __syncthreads();
        if (kb + 2 < nk) {
            int s = (kb + 2) % NSTAGE;
            loadA(s, (kb + 2) * BKH);
            loadB(s, (kb + 2) * BKH);
        }
        asm volatile("cp.async.commit_group;");

        unsigned aStage = aBase + buf * (ASTAGE_H * 2);
        unsigned bStage = bBase + buf * (BSTAGE_H * 2);
        #pragma unroll
        for (int kk = 0; kk < BKH; kk += 16) {
            unsigned a_frag[2][4];
            #pragma unroll
            for (int mt = 0; mt < 2; mt++) {
                asm volatile("ldmatrix.sync.aligned.m8n8.x4.shared.b16 "
                             "{%0,%1,%2,%3}, [%4];"
                             : "=r"(a_frag[mt][0]), "=r"(a_frag[mt][1]),
                               "=r"(a_frag[mt][2]), "=r"(a_frag[mt][3])
                             : "r"(aStage + offA[mt] + kk * 2));
            }
            unsigned b_frag[NT][2];
            #pragma unroll
            for (int p = 0; p < NT / 2; p++) {
                asm volatile("ldmatrix.sync.aligned.m8n8.x4.shared.b16 "
                             "{%0,%1,%2,%3}, [%4];"
                             : "=r"(b_frag[2 * p][0]), "=r"(b_frag[2 * p][1]),
                               "=r"(b_frag[2 * p + 1][0]), "=r"(b_frag[2 * p + 1][1])
                             : "r"(bStage + offB[p] + kk * 2));
            }
            #pragma unroll
            for (int mt = 0; mt < 2; mt++)
                #pragma unroll
                for (int nt = 0; nt < NT; nt++) {
                    asm volatile(
                        "mma.sync.aligned.m16n8k16.row.col.f32.f16.f16.f32 "
                        "{%0,%1,%2,%3}, {%4,%5,%6,%7}, {%8,%9}, {%0,%1,%2,%3};"
                        : "+f"(acc[mt][nt][0]), "+f"(acc[mt][nt][1]),
                          "+f"(acc[mt][nt][2]), "+f"(acc[mt][nt][3])
                        : "r"(a_frag[mt][0]), "r"(a_frag[mt][1]),
                          "r"(a_frag[mt][2]), "r"(a_frag[mt][3]),
                          "r"(b_frag[nt][0]), "r"(b_frag[nt][1]));
                }
        }
        __syncthreads();
        buf = (buf + 1 == NSTAGE) ? 0 : buf + 1;
    }

    #pragma unroll
    for (int mt = 0; mt < 2; mt++) {
        #pragma unroll
        for (int half = 0; half < 2; half++) {
            int gr = rowBase + wm * 32 + mt * 16 + g + half * 8;
            if (gr >= M) continue;
            float dn = (mode == 0) ? degn[gr] : 0.0f;
            #pragma unroll
            for (int nt = 0; nt < NT; nt++) {
                int gc = colBase + wn * (NT * 8) + nt * 8 + q * 2;
                float v0 = acc[mt][nt][half * 2 + 0] + bias[gc];
                float v1 = acc[mt][nt][half * 2 + 1] + bias[gc + 1];
                if (mode == 1) {
                    float* cp = (float*)Cv + (long)gr * N + gc;
                    float2 old = *(const float2*)cp;
                    *(float2*)cp = make_float2(v0 + old.x, v1 + old.y);
                } else {
                    if (mode == 0) {
                        v0 += dn * wdegv[gc];
                        v1 += dn * wdegv[gc + 1];
                    } else {
                        v0 = 0.5f * v0 * (1.0f + erff(v0 * 0.70710678118654752f));
                        v1 = 0.5f * v1 * (1.0f + erff(v1 * 0.70710678118654752f));
                    }
                    __half* cp = (__half*)Cv + (long)gr * N + gc;
                    *(__half2*)cp = __floats2half2_rn(v0, v1);
                }
            }
        }
    }
}
#define SMEM8 (NSTAGE * (ASTAGE_H + 128 * LDH) * (int)sizeof(__half))
#define SMEM4 (NSTAGE * (ASTAGE_H + 64 * LDH) * (int)sizeof(__half))

// ---------------- fused single-pass CSR attention (warp per dst node) ----------
__device__ __forceinline__ float4 ld4h(const __half* p) {
    uint2 u = *(const uint2*)p;
    __half2 h0, h1;
    memcpy(&h0, &u.x, 4);
    memcpy(&h1, &u.y, 4);
    float2 a = __half22float2(h0);
    float2 b = __half22float2(h1);
    return make_float4(a.x, a.y, b.x, b.y);
}

__global__ __launch_bounds__(256) void k_attn(
    const int* __restrict__ off, const int* __restrict__ csr,
    const __half* __restrict__ qkv, __half* __restrict__ aggr) {
    int w = (blockIdx.x * blockDim.x + threadIdx.x) >> 5;
    int lane = threadIdx.x & 31;
    if (w >= NN) return;
    const int beg = off[w], end = off[w + 1];

    float4 qv = ld4h(qkv + (long)w * 384 + lane * 4);

    float s_acc = 0.0f;
    float ax = 0.f, ay = 0.f, az = 0.f, aw = 0.f;
    int e = beg;
    for (; e + 1 < end; e += 2) {
        int s0 = csr[e], s1 = csr[e + 1];
        float4 k0 = ld4h(qkv + (long)s0 * 384 + 128 + lane * 4);
        float4 k1 = ld4h(qkv + (long)s1 * 384 + 128 + lane * 4);
        float4 v0 = ld4h(qkv + (long)s0 * 384 + 256 + lane * 4);
        float4 v1 = ld4h(qkv + (long)s1 * 384 + 256 + lane * 4);
        float p0 = qv.x * k0.x + qv.y * k0.y + qv.z * k0.z + qv.w * k0.w;
        float p1 = qv.x * k1.x + qv.y * k1.y + qv.z * k1.z + qv.w * k1.w;
        p0 += __shfl_xor_sync(0xffffffffu, p0, 1);
        p0 += __shfl_xor_sync(0xffffffffu, p0, 2);
        p1 += __shfl_xor_sync(0xffffffffu, p1, 1);
        p1 += __shfl_xor_sync(0xffffffffu, p1, 2);
        float ex0 = __expf(fminf(fmaxf(p0 * 0.25f, -50.f), 50.f));
        float ex1 = __expf(fminf(fmaxf(p1 * 0.25f, -50.f), 50.f));
        s_acc += ex0 + ex1;
        ax += ex0 * v0.x + ex1 * v1.x;
        ay += ex0 * v0.y + ex1 * v1.y;
        az += ex0 * v0.z + ex1 * v1.z;
        aw += ex0 * v0.w + ex1 * v1.w;
    }
    if (e < end) {
        int s0 = csr[e];
        float4 k0 = ld4h(qkv + (long)s0 * 384 + 128 + lane * 4);
        float4 v0 = ld4h(qkv + (long)s0 * 384 + 256 + lane * 4);
        float p0 = qv.x * k0.x + qv.y * k0.y + qv.z * k0.z + qv.w * k0.w;
        p0 += __shfl_xor_sync(0xffffffffu, p0, 1);
        p0 += __shfl_xor_sync(0xffffffffu, p0, 2);
        float ex0 = __expf(fminf(fmaxf(p0 * 0.25f, -50.f), 50.f));
        s_acc += ex0;
        ax += ex0 * v0.x;
        ay += ex0 * v0.y;
        az += ex0 * v0.z;
        aw += ex0 * v0.w;
    }
    float rs = 1.0f / (s_acc + 1e-16f);
    __half2 h0 = __floats2half2_rn(ax * rs, ay * rs);
    __half2 h1 = __floats2half2_rn(az * rs, aw * rs);
    uint2 u = make_uint2(h2u(h0), h2u(h1));
    *(uint2*)(aggr + (long)w * DD + lane * 4) = u;
}

// ---------------- driver --------------------------------------------------------
extern "C" void kernel_launch(void* const* d_in, const int* in_sizes, int n_in,
                              void* d_out, int out_size) {
    const float* x    = (const float*)d_in[0];
    const int*   ei   = (const int*)d_in[1];
    const float* Wq   = (const float*)d_in[2];
    const float* Wk   = (const float*)d_in[3];
    const float* Wv   = (const float*)d_in[4];
    const float* Wo   = (const float*)d_in[5];
    const float* Wpos = (const float*)d_in[6];
    const float* Wdeg = (const float*)d_in[7];
    const float* W1   = (const float*)d_in[8];
    const float* W2   = (const float*)d_in[9];
    const float* bq   = (const float*)d_in[10];
    const float* bk   = (const float*)d_in[11];
    const float* bv   = (const float*)d_in[12];
    const float* bo   = (const float*)d_in[13];
    const float* bpos = (const float*)d_in[14];
    const float* bdeg = (const float*)d_in[15];
    const float* ln1b = (const float*)d_in[16];
    const float* ln2b = (const float*)d_in[17];
    const float* b1   = (const float*)d_in[18];
    const float* b2   = (const float*)d_in[19];
    const float* ln1g = (const float*)d_in[20];
    const float* ln2g = (const float*)d_in[21];
    float* xbuf = (float*)d_out;

    __half *xn, *qkv, *aggr, *hb, *weff, *wo, *w1, *w2;
    float *deg, *degn, *beff, *wde;
    int *ddeg, *off, *cur, *csr;
    double* stats;
    cudaGetSymbolAddress((void**)&xn,    g_xn);
    cudaGetSymbolAddress((void**)&qkv,   g_qkv);
    cudaGetSymbolAddress((void**)&aggr,  g_aggr);
    cudaGetSymbolAddress((void**)&hb,    g_h);
    cudaGetSymbolAddress((void**)&deg,   g_deg);
    cudaGetSymbolAddress((void**)&degn,  g_degn);
    cudaGetSymbolAddress((void**)&weff,  g_weff);
    cudaGetSymbolAddress((void**)&beff,  g_beff);
    cudaGetSymbolAddress((void**)&wde,   g_wdegeff);
    cudaGetSymbolAddress((void**)&wo,    g_wo);
    cudaGetSymbolAddress((void**)&w1,    g_w1);
    cudaGetSymbolAddress((void**)&w2,    g_w2);
    cudaGetSymbolAddress((void**)&ddeg,  g_ddeg);
    cudaGetSymbolAddress((void**)&off,   g_off);
    cudaGetSymbolAddress((void**)&cur,   g_cur);
    cudaGetSymbolAddress((void**)&csr,   g_csr);
    cudaGetSymbolAddress((void**)&stats, g_stats);

    cudaFuncSetAttribute(gemm_hf<8>, cudaFuncAttributeMaxDynamicSharedMemorySize, SMEM8);
    cudaFuncSetAttribute(gemm_hf<4>, cudaFuncAttributeMaxDynamicSharedMemorySize, SMEM4);

    cudaMemcpyAsync(xbuf, x, (size_t)NN * DD * sizeof(float), cudaMemcpyDeviceToDevice);

    const int rowBlocks = (NN + BM - 1) / BM;
    const int lnBlocks  = (NN + 7) / 8;
    const int nodeWarpBlocks = (NN + 7) / 8;

    // degree stats BEFORE QKV GEMM (deg term folded into GEMM epilogue)
    k_weff<<<3 * DD, DD>>>(Wq, Wk, Wv, Wpos, Wdeg, bq, bk, bv, bpos, bdeg,
                           weff, beff, wde);
    k_layernorm<<<lnBlocks, 256>>>(xbuf, ln1g, ln1b, xn);
    k_prep<<<(NN + 255) / 256, 256>>>(deg, ddeg, stats);
    k_degcount2<<<(EE + 255) / 256, 256>>>(ei, deg, ddeg);
    k_deg_reduce<<<148, 256>>>(deg, stats);
    k_deg_norm<<<(NN + 255) / 256, 256>>>(deg, stats, degn);
    gemm_hf<8><<<dim3(3, rowBlocks), 256, SMEM8>>>(
        xn, weff, qkv, beff, wde, degn, NN, 3 * DD, DD, 0);

    k_scan<<<1, 1024>>>(ddeg, off);
    k_csr_self<<<(NN + 255) / 256, 256>>>(off, cur, csr);
    k_csr_scatter<<<(EE + 255) / 256, 256>>>(ei, cur, csr);

    for (int l = 0; l < LL; l++) {
        k_attn<<<nodeWarpBlocks, 256>>>(off, csr, qkv, aggr);
        k_cvtw<<<(DD * FFD + 255) / 256, 256>>>(Wo + (size_t)l * DD * DD,
                                                W1 + (size_t)l * DD * FFD,
                                                W2 + (size_t)l * FFD * DD, wo, w1, w2);
        gemm_hf<4><<<dim3(2, rowBlocks), 256, SMEM4>>>(
            aggr, wo, xbuf, bo + l * DD, nullptr, nullptr, NN, DD, DD, 1);
        k_layernorm<<<lnBlocks, 256>>>(xbuf, ln2g + l * DD, ln2b + l * DD, xn);
        gemm_hf<8><<<dim3(4, rowBlocks), 256, SMEM8>>>(
            xn, w1, hb, b1 + l * FFD, nullptr, nullptr, NN, FFD, DD, 2);
        gemm_hf<4><<<dim3(2, rowBlocks), 256, SMEM4>>>(
            hb, w2, xbuf, b2 + l * DD, nullptr, nullptr, NN, DD, FFD, 1);
        if (l + 1 < LL) {
            int n = l + 1;
            k_weff<<<3 * DD, DD>>>(Wq + (size_t)n * DD * DD, Wk + (size_t)n * DD * DD,
                                   Wv + (size_t)n * DD * DD, Wpos + (size_t)n * DD * DD,
                                   Wdeg + (size_t)n * DD,
                                   bq + n * DD, bk + n * DD, bv + n * DD,
                                   bpos + n * DD, bdeg + n * DD, weff, beff, wde);
            k_layernorm<<<lnBlocks, 256>>>(xbuf, ln1g + n * DD, ln1b + n * DD, xn);
            gemm_hf<8><<<dim3(3, rowBlocks), 256, SMEM8>>>(
                xn, weff, qkv, beff, wde, degn, NN, 3 * DD, DD, 0);
        }
    }
}